// round 12
// baseline (speedup 1.0000x reference)
#include <cuda_runtime.h>
#include <cuda_bf16.h>
#include <math.h>
#include <stdint.h>

// Problem constants
#define BB   2
#define TT   2048
#define CC   1024
#define NH   16
#define NKV  4
#define HD   64
#define MTOT (BB*TT)          // 4096
#define QKVN 1536             // 1024 + 256 + 256

// ---------------- scratch (device globals; no allocation allowed) ----------
__device__ float g_qkv[MTOT * QKVN];          // x @ [Wq|Wk|Wv] (fp32)
__device__ float g_Y[MTOT * CC];              // attention output [b,t,h,d]
// split-bf16 Q/K/V, [b,h,t,d] layout
__device__ __nv_bfloat16 g_Qh[BB * NH  * TT * HD];
__device__ __nv_bfloat16 g_Ql[BB * NH  * TT * HD];
__device__ __nv_bfloat16 g_Kh[BB * NKV * TT * HD];
__device__ __nv_bfloat16 g_Kl[BB * NKV * TT * HD];
__device__ __nv_bfloat16 g_Vh[BB * NKV * TT * HD];
__device__ __nv_bfloat16 g_Vl[BB * NKV * TT * HD];
// transposed + bf16-split weights: Wt[n][k] (K-major, K=1024)
__device__ __nv_bfloat16 g_wh[QKVN * CC];
__device__ __nv_bfloat16 g_wl[QKVN * CC];
__device__ __nv_bfloat16 g_ph[CC * CC];
__device__ __nv_bfloat16 g_pl[CC * CC];

// ---------------------------------------------------------------------------
__device__ __forceinline__ uint32_t smem_u32(const void* p) {
    uint32_t a;
    asm("{ .reg .u64 t; cvta.to.shared.u64 t, %1; cvt.u32.u64 %0, t; }"
        : "=r"(a) : "l"(p));
    return a;
}

__device__ __forceinline__ void split2(float v, __nv_bfloat16& hi, __nv_bfloat16& lo) {
    hi = __float2bfloat16(v);
    lo = __float2bfloat16(v - __bfloat162float(hi));
}

__device__ __forceinline__ void ldm_x4(uint32_t addr, uint32_t r[4]) {
    asm volatile("ldmatrix.sync.aligned.m8n8.x4.shared.b16 {%0,%1,%2,%3}, [%4];"
        : "=r"(r[0]), "=r"(r[1]), "=r"(r[2]), "=r"(r[3]) : "r"(addr));
}
__device__ __forceinline__ void ldm_x4t(uint32_t addr, uint32_t r[4]) {
    asm volatile("ldmatrix.sync.aligned.m8n8.x4.trans.shared.b16 {%0,%1,%2,%3}, [%4];"
        : "=r"(r[0]), "=r"(r[1]), "=r"(r[2]), "=r"(r[3]) : "r"(addr));
}

__device__ __forceinline__ void mma_bf16(float d[4], const uint32_t a[4],
                                         const uint32_t b[2]) {
    asm volatile(
        "mma.sync.aligned.m16n8k16.row.col.f32.bf16.bf16.f32 "
        "{%0,%1,%2,%3}, {%4,%5,%6,%7}, {%8,%9}, {%0,%1,%2,%3};"
        : "+f"(d[0]), "+f"(d[1]), "+f"(d[2]), "+f"(d[3])
        : "r"(a[0]), "r"(a[1]), "r"(a[2]), "r"(a[3]), "r"(b[0]), "r"(b[1]));
}

__device__ __forceinline__ uint32_t packbf(float e0, float e1) {
    uint32_t r;
    asm("cvt.rn.bf16x2.f32 %0, %1, %2;" : "=r"(r) : "f"(e1), "f"(e0));
    return r;
}

__device__ __forceinline__ void cpa16(uint32_t s, const void* g) {
    asm volatile("cp.async.cg.shared.global [%0], [%1], 16;" :: "r"(s), "l"(g));
}
#define CP_COMMIT() asm volatile("cp.async.commit_group;" ::: "memory")
#define CP_WAIT0()  asm volatile("cp.async.wait_group 0;" ::: "memory")

// ==== merged weight transpose + bf16 split (all 4 matrices, one launch) =====
// z: 0=Wq 1=Wk 2=Wv 3=Wproj.  dst[n0+n][k] = src[k][n]
__global__ void __launch_bounds__(256) wtrans_all_kernel(
    const float* __restrict__ Wq, const float* __restrict__ Wk,
    const float* __restrict__ Wv, const float* __restrict__ Wp,
    __nv_bfloat16* __restrict__ wh, __nv_bfloat16* __restrict__ wl,
    __nv_bfloat16* __restrict__ ph, __nv_bfloat16* __restrict__ pl)
{
    const int z = blockIdx.z;
    const float* src; int N, n0out;
    __nv_bfloat16 *dh, *dl;
    if (z == 0)      { src = Wq; N = 1024; n0out = 0;    dh = wh; dl = wl; }
    else if (z == 1) { src = Wk; N = 256;  n0out = 1024; dh = wh; dl = wl; }
    else if (z == 2) { src = Wv; N = 256;  n0out = 1280; dh = wh; dl = wl; }
    else             { src = Wp; N = 1024; n0out = 0;    dh = ph; dl = pl; }
    if (blockIdx.x * 32 >= N) return;

    __shared__ float t[32][33];
    const int tx = threadIdx.x & 31, ty = threadIdx.x >> 5;
    const int k0 = blockIdx.y * 32, nb = blockIdx.x * 32;
    #pragma unroll
    for (int i = 0; i < 4; i++)
        t[ty + 8 * i][tx] = src[(size_t)(k0 + ty + 8 * i) * N + nb + tx];
    __syncthreads();
    #pragma unroll
    for (int i = 0; i < 4; i++) {
        int nl = ty + 8 * i;
        float v = t[tx][nl];
        __nv_bfloat16 hi, lo; split2(v, hi, lo);
        size_t idx = (size_t)(n0out + nb + nl) * 1024 + k0 + tx;
        dh[idx] = hi; dl[idx] = lo;
    }
}

// ==== split-bf16 mma.sync GEMM, double-buffered (cp.async B, reg-prefetch A)
#define SP 40
#define TS (128 * SP)
#define GEMM_SMEM (8 * TS * 2)

__global__ void __launch_bounds__(256, 2)
tc_gemm(const float* __restrict__ A,
        const __nv_bfloat16* __restrict__ Bh, const __nv_bfloat16* __restrict__ Bl,
        float* __restrict__ C, int K, int ldc)
{
    extern __shared__ __nv_bfloat16 gsm[];

    const int tid  = threadIdx.x;
    const int wid  = tid >> 5;
    const int lane = tid & 31;
    const int m0 = blockIdx.y * 128;
    const int n0 = blockIdx.x * 128;
    const int warp_m = wid & 1;
    const int warp_n = wid >> 1;

    float acc[4][4][4];
    #pragma unroll
    for (int i = 0; i < 4; i++)
        #pragma unroll
        for (int j = 0; j < 4; j++)
            #pragma unroll
            for (int f = 0; f < 4; f++) acc[i][j][f] = 0.f;

    const int lr = tid >> 1;
    const int lh = tid & 1;
    const int soff = lr * SP + lh * 16;

    const float* gA = A + (size_t)(m0 + lr) * K + lh * 16;
    const __nv_bfloat16* gbh = Bh + (size_t)(n0 + lr) * K + lh * 16;
    const __nv_bfloat16* gbl = Bl + (size_t)(n0 + lr) * K + lh * 16;

    const int a_row = warp_m * 64 + (lane & 15);
    const int a_koff = (lane & 16) ? 8 : 0;
    const int b_rowbase = warp_n * 32 + ((lane & 16) >> 1) + (lane & 7);
    const int b_koff = (lane & 8) ? 8 : 0;

    const int nb = K >> 5;

    {
        __nv_bfloat16* bAh = gsm;
        __nv_bfloat16* bAl = gsm + TS;
        #pragma unroll
        for (int j = 0; j < 4; j++) {
            float4 v = *(const float4*)(gA + j * 4);
            __align__(8) __nv_bfloat16 hb[4], lb[4];
            split2(v.x, hb[0], lb[0]); split2(v.y, hb[1], lb[1]);
            split2(v.z, hb[2], lb[2]); split2(v.w, hb[3], lb[3]);
            *(uint2*)(bAh + soff + j * 4) = *(uint2*)hb;
            *(uint2*)(bAl + soff + j * 4) = *(uint2*)lb;
        }
        uint32_t sbh = smem_u32(gsm + 2 * TS + soff);
        uint32_t sbl = smem_u32(gsm + 3 * TS + soff);
        cpa16(sbh,      gbh);     cpa16(sbh + 16, gbh + 8);
        cpa16(sbl,      gbl);     cpa16(sbl + 16, gbl + 8);
        CP_COMMIT();
    }
    CP_WAIT0();
    __syncthreads();

    for (int c = 0; c < nb; c++) {
        const int buf = c & 1;
        __nv_bfloat16* sAh = gsm + buf * 4 * TS;
        __nv_bfloat16* sAl = sAh + TS;
        __nv_bfloat16* sBh = sAh + 2 * TS;
        __nv_bfloat16* sBl = sAh + 3 * TS;
        __nv_bfloat16* nAh = gsm + (buf ^ 1) * 4 * TS;
        __nv_bfloat16* nAl = nAh + TS;

        float4 av[4];
        const bool more = (c + 1 < nb);
        if (more) {
            const int kc = (c + 1) << 5;
            #pragma unroll
            for (int j = 0; j < 4; j++) av[j] = *(const float4*)(gA + kc + j * 4);
            uint32_t sbh = smem_u32(nAh + 2 * TS + soff);
            uint32_t sbl = smem_u32(nAh + 3 * TS + soff);
            cpa16(sbh,      gbh + kc);     cpa16(sbh + 16, gbh + kc + 8);
            cpa16(sbl,      gbl + kc);     cpa16(sbl + 16, gbl + kc + 8);
            CP_COMMIT();
        }

        #pragma unroll
        for (int kk = 0; kk < 32; kk += 16) {
            uint32_t bh[4][2], bl[4][2];
            #pragma unroll
            for (int p = 0; p < 2; p++) {
                uint32_t r[4];
                uint32_t ad = smem_u32(&sBh[(b_rowbase + p * 16) * SP + kk + b_koff]);
                ldm_x4(ad, r);
                bh[p*2][0] = r[0]; bh[p*2][1] = r[1];
                bh[p*2+1][0] = r[2]; bh[p*2+1][1] = r[3];
                ad = smem_u32(&sBl[(b_rowbase + p * 16) * SP + kk + b_koff]);
                ldm_x4(ad, r);
                bl[p*2][0] = r[0]; bl[p*2][1] = r[1];
                bl[p*2+1][0] = r[2]; bl[p*2+1][1] = r[3];
            }
            #pragma unroll
            for (int mi = 0; mi < 4; mi++) {
                uint32_t ah[4], al[4];
                uint32_t ad = smem_u32(&sAh[(a_row + mi * 16) * SP + kk + a_koff]);
                ldm_x4(ad, ah);
                ad = smem_u32(&sAl[(a_row + mi * 16) * SP + kk + a_koff]);
                ldm_x4(ad, al);
                #pragma unroll
                for (int nj = 0; nj < 4; nj++) {
                    mma_bf16(acc[mi][nj], ah, bh[nj]);
                    mma_bf16(acc[mi][nj], ah, bl[nj]);
                    mma_bf16(acc[mi][nj], al, bh[nj]);
                }
            }
        }

        if (more) {
            #pragma unroll
            for (int j = 0; j < 4; j++) {
                __align__(8) __nv_bfloat16 hb[4], lb[4];
                split2(av[j].x, hb[0], lb[0]); split2(av[j].y, hb[1], lb[1]);
                split2(av[j].z, hb[2], lb[2]); split2(av[j].w, hb[3], lb[3]);
                *(uint2*)(nAh + soff + j * 4) = *(uint2*)hb;
                *(uint2*)(nAl + soff + j * 4) = *(uint2*)lb;
            }
        }
        CP_WAIT0();
        __syncthreads();
    }

    const int gid = lane >> 2, tig = lane & 3;
    #pragma unroll
    for (int mi = 0; mi < 4; mi++) {
        int row = m0 + warp_m * 64 + mi * 16 + gid;
        #pragma unroll
        for (int nj = 0; nj < 4; nj++) {
            int col = n0 + warp_n * 32 + nj * 8 + tig * 2;
            *(float2*)&C[(size_t)row * ldc + col] =
                make_float2(acc[mi][nj][0], acc[mi][nj][1]);
            *(float2*)&C[(size_t)(row + 8) * ldc + col] =
                make_float2(acc[mi][nj][2], acc[mi][nj][3]);
        }
    }
}

// -------- pointwise: gate + ve, RoPE, RMSNorm*1.2, split-bf16 output --------
__global__ void __launch_bounds__(128) pointwise_kernel(
    const float* __restrict__ x,
    const float* __restrict__ ve,
    const float* __restrict__ cosb,
    const float* __restrict__ sinb,
    const float* __restrict__ Wg)
{
    const int bt   = blockIdx.x;
    const int b    = bt >> 11;
    const int t    = bt & (TT - 1);
    const int tid  = threadIdx.x;
    const int w    = tid >> 5;
    const int lane = tid & 31;

    float p = (lane < 12) ? x[bt * CC + lane] * Wg[lane * NKV + w] : 0.f;
    #pragma unroll
    for (int o = 16; o; o >>= 1) p += __shfl_xor_sync(0xffffffffu, p, o);
    const float gate = 3.f / (1.f + __expf(-p));

    const float c = cosb[t * 32 + lane];
    const float s = sinb[t * 32 + lane];
    const float* qkv = &g_qkv[bt * QKVN];

    for (int h = w; h < NH; h += 4) {
        float x1 = qkv[h * HD + lane];
        float x2 = qkv[h * HD + 32 + lane];
        float y1 =  x1 * c + x2 * s;
        float y2 = -x1 * s + x2 * c;
        float ss = y1 * y1 + y2 * y2;
        #pragma unroll
        for (int o = 16; o; o >>= 1) ss += __shfl_xor_sync(0xffffffffu, ss, o);
        float r = rsqrtf(ss * (1.f / 64.f) + 1e-6f) * 1.2f;
        size_t base = ((size_t)(b * NH + h) * TT + t) * HD;
        __nv_bfloat16 hi, lo;
        split2(y1 * r, hi, lo); g_Qh[base + lane]      = hi; g_Ql[base + lane]      = lo;
        split2(y2 * r, hi, lo); g_Qh[base + lane + 32] = hi; g_Ql[base + lane + 32] = lo;
    }
    {
        float x1 = qkv[1024 + w * HD + lane];
        float x2 = qkv[1024 + w * HD + 32 + lane];
        float y1 =  x1 * c + x2 * s;
        float y2 = -x1 * s + x2 * c;
        float ss = y1 * y1 + y2 * y2;
        #pragma unroll
        for (int o = 16; o; o >>= 1) ss += __shfl_xor_sync(0xffffffffu, ss, o);
        float r = rsqrtf(ss * (1.f / 64.f) + 1e-6f) * 1.2f;
        size_t base = ((size_t)(b * NKV + w) * TT + t) * HD;
        __nv_bfloat16 hi, lo;
        split2(y1 * r, hi, lo); g_Kh[base + lane]      = hi; g_Kl[base + lane]      = lo;
        split2(y2 * r, hi, lo); g_Kh[base + lane + 32] = hi; g_Kl[base + lane + 32] = lo;
    }
    {
        float v1 = qkv[1280 + w * HD + lane]      + gate * ve[bt * (NKV * HD) + w * HD + lane];
        float v2 = qkv[1280 + w * HD + 32 + lane] + gate * ve[bt * (NKV * HD) + w * HD + 32 + lane];
        size_t base = ((size_t)(b * NKV + w) * TT + t) * HD;
        __nv_bfloat16 hi, lo;
        split2(v1, hi, lo); g_Vh[base + lane]      = hi; g_Vl[base + lane]      = lo;
        split2(v2, hi, lo); g_Vh[base + lane + 32] = hi; g_Vl[base + lane + 32] = lo;
    }
}

// ==== tensor-core flash attention: 128 q-rows/CTA, 8 warps, dbuf K/V ========
#define AP 72
#define AQS (128 * AP)                   // Q array elems
#define AKS (64 * AP)                    // K/V tile array elems
#define ATT_SMEM ((2 * AQS + 8 * AKS) * 2)
// score scale with log2(e) folded in: softmax uses exp2
#define ESC 0.1803368801111204f          // 0.125 * log2(e)

__global__ void __launch_bounds__(256) attn_tc_kernel(const void* __restrict__ winptr)
{
    extern __shared__ __nv_bfloat16 smb[];
    __nv_bfloat16* sQh = smb;
    __nv_bfloat16* sQl = smb + AQS;

    // heavy q-tiles first: better wave packing
    const int q0 = (gridDim.x - 1 - blockIdx.x) * 128;
    const int h  = blockIdx.y;
    const int b  = blockIdx.z;
    const int kh = h >> 2;

    const int tid = threadIdx.x, w = tid >> 5, lane = tid & 31;

    int  wi = *(const int*)winptr;
    float wf = *(const float*)winptr;
    const int W = (wi > 0 && wi < (1 << 20)) ? wi : (int)wf;

    const size_t kvbase = (size_t)(b * NKV + kh) * TT * HD;

    const int kr = tid >> 2, kq = tid & 3;
    const uint32_t ksoff = (uint32_t)(kr * AP + kq * 16) * 2;

    int kbeg = q0 - W; if (kbeg < 0) kbeg = 0;
    const int kstart = (kbeg / 64) * 64;
    const int klast  = q0 + 64;

    auto issue_tile = [&](int k0, int bf) {
        const size_t g = kvbase + (size_t)(k0 + kr) * HD + kq * 16;
        uint32_t base = smem_u32(smb + 2 * AQS + bf * 4 * AKS) + ksoff;
        const __nv_bfloat16* srcs[4] = { g_Kh + g, g_Kl + g, g_Vh + g, g_Vl + g };
        #pragma unroll
        for (int a = 0; a < 4; a++) {
            cpa16(base + a * AKS * 2,      srcs[a]);
            cpa16(base + a * AKS * 2 + 16, srcs[a] + 8);
        }
    };

    {
        const int lr = tid >> 1, lhf = tid & 1;
        size_t gq = ((size_t)(b * NH + h) * TT + q0 + lr) * HD + lhf * 32;
        #pragma unroll
        for (int j = 0; j < 4; j++) {
            *(uint4*)&sQh[lr * AP + lhf * 32 + j * 8] = *(const uint4*)&g_Qh[gq + j * 8];
            *(uint4*)&sQl[lr * AP + lhf * 32 + j * 8] = *(const uint4*)&g_Ql[gq + j * 8];
        }
    }
    issue_tile(kstart, 0);
    CP_COMMIT();
    __syncthreads();

    uint32_t qh[4][4], ql[4][4];
    {
        const int qrow = w * 16 + (lane & 15);
        #pragma unroll
        for (int ks = 0; ks < 4; ks++) {
            int col = ks * 16 + ((lane & 16) ? 8 : 0);
            ldm_x4(smem_u32(&sQh[qrow * AP + col]), qh[ks]);
            ldm_x4(smem_u32(&sQl[qrow * AP + col]), ql[ks]);
        }
    }

    float o[8][4];
    #pragma unroll
    for (int d = 0; d < 8; d++)
        #pragma unroll
        for (int e = 0; e < 4; e++) o[d][e] = 0.f;
    float m_lo = -INFINITY, m_hi = -INFINITY, l_lo = 0.f, l_hi = 0.f;

    const int wmin = q0 + w * 16;
    const int wmax = wmin + 15;
    const int row_lo = wmin + (lane >> 2);
    const int row_hi = row_lo + 8;
    const int colb   = (lane & 3) * 2;

    int buf = 0;
    for (int k0 = kstart; k0 <= klast; k0 += 64) {
        CP_WAIT0();
        __syncthreads();
        if (k0 + 64 <= klast) {
            issue_tile(k0 + 64, buf ^ 1);
            CP_COMMIT();
        }

        const bool active = (k0 <= wmax) && (k0 + 63 >= wmin - W);
        if (active) {
            __nv_bfloat16* sKh = smb + 2 * AQS + buf * 4 * AKS;
            __nv_bfloat16* sKl = sKh + AKS;
            __nv_bfloat16* sVh = sKh + 2 * AKS;
            __nv_bfloat16* sVl = sKh + 3 * AKS;

            float s[8][4];
            #pragma unroll
            for (int nj = 0; nj < 8; nj++)
                #pragma unroll
                for (int e = 0; e < 4; e++) s[nj][e] = 0.f;

            #pragma unroll
            for (int ks = 0; ks < 4; ks++) {
                #pragma unroll
                for (int nt = 0; nt < 4; nt++) {
                    int krow = nt * 16 + ((lane & 16) >> 1) + (lane & 7);
                    int col  = ks * 16 + ((lane & 8) ? 8 : 0);
                    uint32_t rh[4], rl[4];
                    ldm_x4(smem_u32(&sKh[krow * AP + col]), rh);
                    ldm_x4(smem_u32(&sKl[krow * AP + col]), rl);
                    #pragma unroll
                    for (int e = 0; e < 2; e++) {
                        uint32_t bhf[2] = { rh[e*2], rh[e*2+1] };
                        uint32_t blf[2] = { rl[e*2], rl[e*2+1] };
                        mma_bf16(s[nt*2+e], qh[ks], bhf);
                        mma_bf16(s[nt*2+e], ql[ks], bhf);
                        mma_bf16(s[nt*2+e], qh[ks], blf);
                    }
                }
            }

            // mask + scale into log2 domain
            #pragma unroll
            for (int nj = 0; nj < 8; nj++) {
                #pragma unroll
                for (int e = 0; e < 4; e++) {
                    int col = k0 + nj * 8 + colb + (e & 1);
                    int row = (e < 2) ? row_lo : row_hi;
                    bool ok = (col <= row) && (row - col <= W);
                    s[nj][e] = ok ? s[nj][e] * ESC : -3e9f;
                }
            }

            float mx_lo = -INFINITY, mx_hi = -INFINITY;
            #pragma unroll
            for (int nj = 0; nj < 8; nj++) {
                mx_lo = fmaxf(mx_lo, fmaxf(s[nj][0], s[nj][1]));
                mx_hi = fmaxf(mx_hi, fmaxf(s[nj][2], s[nj][3]));
            }
            mx_lo = fmaxf(mx_lo, __shfl_xor_sync(0xffffffffu, mx_lo, 1));
            mx_lo = fmaxf(mx_lo, __shfl_xor_sync(0xffffffffu, mx_lo, 2));
            mx_hi = fmaxf(mx_hi, __shfl_xor_sync(0xffffffffu, mx_hi, 1));
            mx_hi = fmaxf(mx_hi, __shfl_xor_sync(0xffffffffu, mx_hi, 2));

            float mnew_lo = fmaxf(fmaxf(m_lo, mx_lo), -1e9f);
            float mnew_hi = fmaxf(fmaxf(m_hi, mx_hi), -1e9f);
            float sc_lo = exp2f(m_lo - mnew_lo);
            float sc_hi = exp2f(m_hi - mnew_hi);
            m_lo = mnew_lo; m_hi = mnew_hi;

            float sum_lo = 0.f, sum_hi = 0.f;
            #pragma unroll
            for (int nj = 0; nj < 8; nj++) {
                s[nj][0] = exp2f(s[nj][0] - mnew_lo);
                s[nj][1] = exp2f(s[nj][1] - mnew_lo);
                s[nj][2] = exp2f(s[nj][2] - mnew_hi);
                s[nj][3] = exp2f(s[nj][3] - mnew_hi);
                sum_lo += s[nj][0] + s[nj][1];
                sum_hi += s[nj][2] + s[nj][3];
            }
            sum_lo += __shfl_xor_sync(0xffffffffu, sum_lo, 1);
            sum_lo += __shfl_xor_sync(0xffffffffu, sum_lo, 2);
            sum_hi += __shfl_xor_sync(0xffffffffu, sum_hi, 1);
            sum_hi += __shfl_xor_sync(0xffffffffu, sum_hi, 2);
            l_lo = l_lo * sc_lo + sum_lo;
            l_hi = l_hi * sc_hi + sum_hi;

            #pragma unroll
            for (int d = 0; d < 8; d++) {
                o[d][0] *= sc_lo; o[d][1] *= sc_lo;
                o[d][2] *= sc_hi; o[d][3] *= sc_hi;
            }

            uint32_t ph[4][4], pl[4][4];
            #pragma unroll
            for (int ks = 0; ks < 4; ks++) {
                #pragma unroll
                for (int e = 0; e < 2; e++) {
                    int nj = ks * 2 + e;
                    float p0 = s[nj][0], p1 = s[nj][1], p2 = s[nj][2], p3 = s[nj][3];
                    uint32_t h01 = packbf(p0, p1);
                    uint32_t h23 = packbf(p2, p3);
                    __nv_bfloat162 hb01 = *(__nv_bfloat162*)&h01;
                    __nv_bfloat162 hb23 = *(__nv_bfloat162*)&h23;
                    uint32_t l01 = packbf(p0 - __bfloat162float(hb01.x),
                                          p1 - __bfloat162float(hb01.y));
                    uint32_t l23 = packbf(p2 - __bfloat162float(hb23.x),
                                          p3 - __bfloat162float(hb23.y));
                    ph[ks][e*2]   = h01; ph[ks][e*2+1] = h23;
                    pl[ks][e*2]   = l01; pl[ks][e*2+1] = l23;
                }
            }

            #pragma unroll
            for (int ks = 0; ks < 4; ks++) {
                #pragma unroll
                for (int dt = 0; dt < 4; dt++) {
                    int vrow = ks * 16 + (lane & 15);
                    int vcol = dt * 16 + ((lane & 16) ? 8 : 0);
                    uint32_t rh[4], rl[4];
                    ldm_x4t(smem_u32(&sVh[vrow * AP + vcol]), rh);
                    ldm_x4t(smem_u32(&sVl[vrow * AP + vcol]), rl);
                    #pragma unroll
                    for (int e = 0; e < 2; e++) {
                        uint32_t bhf[2] = { rh[e*2], rh[e*2+1] };
                        uint32_t blf[2] = { rl[e*2], rl[e*2+1] };
                        mma_bf16(o[dt*2+e], ph[ks], bhf);
                        mma_bf16(o[dt*2+e], pl[ks], bhf);
                        mma_bf16(o[dt*2+e], ph[ks], blf);
                    }
                }
            }
        }
        buf ^= 1;
    }

    float li_lo = 1.f / l_lo, li_hi = 1.f / l_hi;
    #pragma unroll
    for (int d = 0; d < 8; d++) {
        int col = h * HD + d * 8 + colb;
        *(float2*)&g_Y[(size_t)(b * TT + row_lo) * CC + col] =
            make_float2(o[d][0] * li_lo, o[d][1] * li_lo);
        *(float2*)&g_Y[(size_t)(b * TT + row_hi) * CC + col] =
            make_float2(o[d][2] * li_hi, o[d][3] * li_hi);
    }
}

// ---------------------------------------------------------------------------
extern "C" void kernel_launch(void* const* d_in, const int* in_sizes, int n_in,
                              void* d_out, int out_size)
{
    const float* x    = (const float*)d_in[0];
    const float* ve   = (const float*)d_in[1];
    const float* cosb = (const float*)d_in[2];
    const float* sinb = (const float*)d_in[3];
    const float* Wq   = (const float*)d_in[4];
    const float* Wk   = (const float*)d_in[5];
    const float* Wv   = (const float*)d_in[6];
    const float* Wp   = (const float*)d_in[7];
    const float* Wg   = (const float*)d_in[8];
    const void*  win  = d_in[9];
    float* out = (float*)d_out;

    cudaFuncSetAttribute(attn_tc_kernel, cudaFuncAttributeMaxDynamicSharedMemorySize,
                         ATT_SMEM);
    cudaFuncSetAttribute(tc_gemm, cudaFuncAttributeMaxDynamicSharedMemorySize,
                         GEMM_SMEM);

    __nv_bfloat16 *wh, *wl, *ph, *pl;
    cudaGetSymbolAddress((void**)&wh, g_wh);
    cudaGetSymbolAddress((void**)&wl, g_wl);
    cudaGetSymbolAddress((void**)&ph, g_ph);
    cudaGetSymbolAddress((void**)&pl, g_pl);
    float *qkvp, *Yp;
    cudaGetSymbolAddress((void**)&qkvp, g_qkv);
    cudaGetSymbolAddress((void**)&Yp, g_Y);

    // all weight transposes in ONE launch
    wtrans_all_kernel<<<dim3(32, 32, 4), 256>>>(Wq, Wk, Wv, Wp, wh, wl, ph, pl);

    // qkv = x @ [Wq|Wk|Wv]
    tc_gemm<<<dim3(12, 32), 256, GEMM_SMEM>>>(x, wh, wl, qkvp, 1024, QKVN);

    pointwise_kernel<<<MTOT, 128>>>(x, ve, cosb, sinb, Wg);

    attn_tc_kernel<<<dim3(TT / 128, NH, BB), 256, ATT_SMEM>>>(win);

    // out = Y @ Wproj
    tc_gemm<<<dim3(8, 32), 256, GEMM_SMEM>>>(Yp, ph, pl, out, 1024, 1024);
}

// round 13
// speedup vs baseline: 1.5391x; 1.5391x over previous
#include <cuda_runtime.h>
#include <cuda_bf16.h>
#include <math.h>
#include <stdint.h>

// Problem constants
#define BB   2
#define TT   2048
#define CC   1024
#define NH   16
#define NKV  4
#define HD   64
#define MTOT (BB*TT)          // 4096
#define QKVN 1536             // 1024 + 256 + 256

// ---------------- scratch (device globals; no allocation allowed) ----------
__device__ float g_qkv[MTOT * QKVN];          // x @ [Wq|Wk|Wv] (fp32)
__device__ float g_Y[MTOT * CC];              // attention output [b,t,h,d]
// split-bf16 Q/K/V, [b,h,t,d] layout
__device__ __nv_bfloat16 g_Qh[BB * NH  * TT * HD];
__device__ __nv_bfloat16 g_Ql[BB * NH  * TT * HD];
__device__ __nv_bfloat16 g_Kh[BB * NKV * TT * HD];
__device__ __nv_bfloat16 g_Kl[BB * NKV * TT * HD];
__device__ __nv_bfloat16 g_Vh[BB * NKV * TT * HD];
__device__ __nv_bfloat16 g_Vl[BB * NKV * TT * HD];
// transposed + bf16-split weights: Wt[n][k] (K-major, K=1024)
__device__ __nv_bfloat16 g_wh[QKVN * CC];
__device__ __nv_bfloat16 g_wl[QKVN * CC];
__device__ __nv_bfloat16 g_ph[CC * CC];
__device__ __nv_bfloat16 g_pl[CC * CC];

// ---------------------------------------------------------------------------
__device__ __forceinline__ uint32_t smem_u32(const void* p) {
    uint32_t a;
    asm("{ .reg .u64 t; cvta.to.shared.u64 t, %1; cvt.u32.u64 %0, t; }"
        : "=r"(a) : "l"(p));
    return a;
}

__device__ __forceinline__ void split2(float v, __nv_bfloat16& hi, __nv_bfloat16& lo) {
    hi = __float2bfloat16(v);
    lo = __float2bfloat16(v - __bfloat162float(hi));
}

__device__ __forceinline__ void ldm_x4(uint32_t addr, uint32_t r[4]) {
    asm volatile("ldmatrix.sync.aligned.m8n8.x4.shared.b16 {%0,%1,%2,%3}, [%4];"
        : "=r"(r[0]), "=r"(r[1]), "=r"(r[2]), "=r"(r[3]) : "r"(addr));
}
__device__ __forceinline__ void ldm_x4t(uint32_t addr, uint32_t r[4]) {
    asm volatile("ldmatrix.sync.aligned.m8n8.x4.trans.shared.b16 {%0,%1,%2,%3}, [%4];"
        : "=r"(r[0]), "=r"(r[1]), "=r"(r[2]), "=r"(r[3]) : "r"(addr));
}

__device__ __forceinline__ void mma_bf16(float d[4], const uint32_t a[4],
                                         const uint32_t b[2]) {
    asm volatile(
        "mma.sync.aligned.m16n8k16.row.col.f32.bf16.bf16.f32 "
        "{%0,%1,%2,%3}, {%4,%5,%6,%7}, {%8,%9}, {%0,%1,%2,%3};"
        : "+f"(d[0]), "+f"(d[1]), "+f"(d[2]), "+f"(d[3])
        : "r"(a[0]), "r"(a[1]), "r"(a[2]), "r"(a[3]), "r"(b[0]), "r"(b[1]));
}

__device__ __forceinline__ uint32_t packbf(float e0, float e1) {
    uint32_t r;
    asm("cvt.rn.bf16x2.f32 %0, %1, %2;" : "=r"(r) : "f"(e1), "f"(e0));
    return r;
}

// fast exp2: single MUFU.EX2 (exp2f without fast-math is a slow softpath!)
__device__ __forceinline__ float ex2(float x) {
    float y;
    asm("ex2.approx.ftz.f32 %0, %1;" : "=f"(y) : "f"(x));
    return y;
}

__device__ __forceinline__ void cpa16(uint32_t s, const void* g) {
    asm volatile("cp.async.cg.shared.global [%0], [%1], 16;" :: "r"(s), "l"(g));
}
#define CP_COMMIT() asm volatile("cp.async.commit_group;" ::: "memory")
#define CP_WAIT0()  asm volatile("cp.async.wait_group 0;" ::: "memory")

// ==== merged weight transpose + bf16 split (all 4 matrices, one launch) =====
__global__ void __launch_bounds__(256) wtrans_all_kernel(
    const float* __restrict__ Wq, const float* __restrict__ Wk,
    const float* __restrict__ Wv, const float* __restrict__ Wp,
    __nv_bfloat16* __restrict__ wh, __nv_bfloat16* __restrict__ wl,
    __nv_bfloat16* __restrict__ ph, __nv_bfloat16* __restrict__ pl)
{
    const int z = blockIdx.z;
    const float* src; int N, n0out;
    __nv_bfloat16 *dh, *dl;
    if (z == 0)      { src = Wq; N = 1024; n0out = 0;    dh = wh; dl = wl; }
    else if (z == 1) { src = Wk; N = 256;  n0out = 1024; dh = wh; dl = wl; }
    else if (z == 2) { src = Wv; N = 256;  n0out = 1280; dh = wh; dl = wl; }
    else             { src = Wp; N = 1024; n0out = 0;    dh = ph; dl = pl; }
    if (blockIdx.x * 32 >= N) return;

    __shared__ float t[32][33];
    const int tx = threadIdx.x & 31, ty = threadIdx.x >> 5;
    const int k0 = blockIdx.y * 32, nb = blockIdx.x * 32;
    #pragma unroll
    for (int i = 0; i < 4; i++)
        t[ty + 8 * i][tx] = src[(size_t)(k0 + ty + 8 * i) * N + nb + tx];
    __syncthreads();
    #pragma unroll
    for (int i = 0; i < 4; i++) {
        int nl = ty + 8 * i;
        float v = t[tx][nl];
        __nv_bfloat16 hi, lo; split2(v, hi, lo);
        size_t idx = (size_t)(n0out + nb + nl) * 1024 + k0 + tx;
        dh[idx] = hi; dl[idx] = lo;
    }
}

// ==== split-bf16 mma.sync GEMM, double-buffered (cp.async B, reg-prefetch A)
#define SP 40
#define TS (128 * SP)
#define GEMM_SMEM (8 * TS * 2)

__global__ void __launch_bounds__(256, 2)
tc_gemm(const float* __restrict__ A,
        const __nv_bfloat16* __restrict__ Bh, const __nv_bfloat16* __restrict__ Bl,
        float* __restrict__ C, int K, int ldc)
{
    extern __shared__ __nv_bfloat16 gsm[];

    const int tid  = threadIdx.x;
    const int wid  = tid >> 5;
    const int lane = tid & 31;
    const int m0 = blockIdx.y * 128;
    const int n0 = blockIdx.x * 128;
    const int warp_m = wid & 1;
    const int warp_n = wid >> 1;

    float acc[4][4][4];
    #pragma unroll
    for (int i = 0; i < 4; i++)
        #pragma unroll
        for (int j = 0; j < 4; j++)
            #pragma unroll
            for (int f = 0; f < 4; f++) acc[i][j][f] = 0.f;

    const int lr = tid >> 1;
    const int lh = tid & 1;
    const int soff = lr * SP + lh * 16;

    const float* gA = A + (size_t)(m0 + lr) * K + lh * 16;
    const __nv_bfloat16* gbh = Bh + (size_t)(n0 + lr) * K + lh * 16;
    const __nv_bfloat16* gbl = Bl + (size_t)(n0 + lr) * K + lh * 16;

    const int a_row = warp_m * 64 + (lane & 15);
    const int a_koff = (lane & 16) ? 8 : 0;
    const int b_rowbase = warp_n * 32 + ((lane & 16) >> 1) + (lane & 7);
    const int b_koff = (lane & 8) ? 8 : 0;

    const int nb = K >> 5;

    {
        __nv_bfloat16* bAh = gsm;
        __nv_bfloat16* bAl = gsm + TS;
        #pragma unroll
        for (int j = 0; j < 4; j++) {
            float4 v = *(const float4*)(gA + j * 4);
            __align__(8) __nv_bfloat16 hb[4], lb[4];
            split2(v.x, hb[0], lb[0]); split2(v.y, hb[1], lb[1]);
            split2(v.z, hb[2], lb[2]); split2(v.w, hb[3], lb[3]);
            *(uint2*)(bAh + soff + j * 4) = *(uint2*)hb;
            *(uint2*)(bAl + soff + j * 4) = *(uint2*)lb;
        }
        uint32_t sbh = smem_u32(gsm + 2 * TS + soff);
        uint32_t sbl = smem_u32(gsm + 3 * TS + soff);
        cpa16(sbh,      gbh);     cpa16(sbh + 16, gbh + 8);
        cpa16(sbl,      gbl);     cpa16(sbl + 16, gbl + 8);
        CP_COMMIT();
    }
    CP_WAIT0();
    __syncthreads();

    for (int c = 0; c < nb; c++) {
        const int buf = c & 1;
        __nv_bfloat16* sAh = gsm + buf * 4 * TS;
        __nv_bfloat16* sAl = sAh + TS;
        __nv_bfloat16* sBh = sAh + 2 * TS;
        __nv_bfloat16* sBl = sAh + 3 * TS;
        __nv_bfloat16* nAh = gsm + (buf ^ 1) * 4 * TS;
        __nv_bfloat16* nAl = nAh + TS;

        float4 av[4];
        const bool more = (c + 1 < nb);
        if (more) {
            const int kc = (c + 1) << 5;
            #pragma unroll
            for (int j = 0; j < 4; j++) av[j] = *(const float4*)(gA + kc + j * 4);
            uint32_t sbh = smem_u32(nAh + 2 * TS + soff);
            uint32_t sbl = smem_u32(nAh + 3 * TS + soff);
            cpa16(sbh,      gbh + kc);     cpa16(sbh + 16, gbh + kc + 8);
            cpa16(sbl,      gbl + kc);     cpa16(sbl + 16, gbl + kc + 8);
            CP_COMMIT();
        }

        #pragma unroll
        for (int kk = 0; kk < 32; kk += 16) {
            uint32_t bh[4][2], bl[4][2];
            #pragma unroll
            for (int p = 0; p < 2; p++) {
                uint32_t r[4];
                uint32_t ad = smem_u32(&sBh[(b_rowbase + p * 16) * SP + kk + b_koff]);
                ldm_x4(ad, r);
                bh[p*2][0] = r[0]; bh[p*2][1] = r[1];
                bh[p*2+1][0] = r[2]; bh[p*2+1][1] = r[3];
                ad = smem_u32(&sBl[(b_rowbase + p * 16) * SP + kk + b_koff]);
                ldm_x4(ad, r);
                bl[p*2][0] = r[0]; bl[p*2][1] = r[1];
                bl[p*2+1][0] = r[2]; bl[p*2+1][1] = r[3];
            }
            #pragma unroll
            for (int mi = 0; mi < 4; mi++) {
                uint32_t ah[4], al[4];
                uint32_t ad = smem_u32(&sAh[(a_row + mi * 16) * SP + kk + a_koff]);
                ldm_x4(ad, ah);
                ad = smem_u32(&sAl[(a_row + mi * 16) * SP + kk + a_koff]);
                ldm_x4(ad, al);
                #pragma unroll
                for (int nj = 0; nj < 4; nj++) {
                    mma_bf16(acc[mi][nj], ah, bh[nj]);
                    mma_bf16(acc[mi][nj], ah, bl[nj]);
                    mma_bf16(acc[mi][nj], al, bh[nj]);
                }
            }
        }

        if (more) {
            #pragma unroll
            for (int j = 0; j < 4; j++) {
                __align__(8) __nv_bfloat16 hb[4], lb[4];
                split2(av[j].x, hb[0], lb[0]); split2(av[j].y, hb[1], lb[1]);
                split2(av[j].z, hb[2], lb[2]); split2(av[j].w, hb[3], lb[3]);
                *(uint2*)(nAh + soff + j * 4) = *(uint2*)hb;
                *(uint2*)(nAl + soff + j * 4) = *(uint2*)lb;
            }
        }
        CP_WAIT0();
        __syncthreads();
    }

    const int gid = lane >> 2, tig = lane & 3;
    #pragma unroll
    for (int mi = 0; mi < 4; mi++) {
        int row = m0 + warp_m * 64 + mi * 16 + gid;
        #pragma unroll
        for (int nj = 0; nj < 4; nj++) {
            int col = n0 + warp_n * 32 + nj * 8 + tig * 2;
            *(float2*)&C[(size_t)row * ldc + col] =
                make_float2(acc[mi][nj][0], acc[mi][nj][1]);
            *(float2*)&C[(size_t)(row + 8) * ldc + col] =
                make_float2(acc[mi][nj][2], acc[mi][nj][3]);
        }
    }
}

// -------- pointwise: gate + ve, RoPE, RMSNorm*1.2, split-bf16 output --------
__global__ void __launch_bounds__(128) pointwise_kernel(
    const float* __restrict__ x,
    const float* __restrict__ ve,
    const float* __restrict__ cosb,
    const float* __restrict__ sinb,
    const float* __restrict__ Wg)
{
    const int bt   = blockIdx.x;
    const int b    = bt >> 11;
    const int t    = bt & (TT - 1);
    const int tid  = threadIdx.x;
    const int w    = tid >> 5;
    const int lane = tid & 31;

    float p = (lane < 12) ? x[bt * CC + lane] * Wg[lane * NKV + w] : 0.f;
    #pragma unroll
    for (int o = 16; o; o >>= 1) p += __shfl_xor_sync(0xffffffffu, p, o);
    const float gate = 3.f / (1.f + __expf(-p));

    const float c = cosb[t * 32 + lane];
    const float s = sinb[t * 32 + lane];
    const float* qkv = &g_qkv[bt * QKVN];

    for (int h = w; h < NH; h += 4) {
        float x1 = qkv[h * HD + lane];
        float x2 = qkv[h * HD + 32 + lane];
        float y1 =  x1 * c + x2 * s;
        float y2 = -x1 * s + x2 * c;
        float ss = y1 * y1 + y2 * y2;
        #pragma unroll
        for (int o = 16; o; o >>= 1) ss += __shfl_xor_sync(0xffffffffu, ss, o);
        float r = rsqrtf(ss * (1.f / 64.f) + 1e-6f) * 1.2f;
        size_t base = ((size_t)(b * NH + h) * TT + t) * HD;
        __nv_bfloat16 hi, lo;
        split2(y1 * r, hi, lo); g_Qh[base + lane]      = hi; g_Ql[base + lane]      = lo;
        split2(y2 * r, hi, lo); g_Qh[base + lane + 32] = hi; g_Ql[base + lane + 32] = lo;
    }
    {
        float x1 = qkv[1024 + w * HD + lane];
        float x2 = qkv[1024 + w * HD + 32 + lane];
        float y1 =  x1 * c + x2 * s;
        float y2 = -x1 * s + x2 * c;
        float ss = y1 * y1 + y2 * y2;
        #pragma unroll
        for (int o = 16; o; o >>= 1) ss += __shfl_xor_sync(0xffffffffu, ss, o);
        float r = rsqrtf(ss * (1.f / 64.f) + 1e-6f) * 1.2f;
        size_t base = ((size_t)(b * NKV + w) * TT + t) * HD;
        __nv_bfloat16 hi, lo;
        split2(y1 * r, hi, lo); g_Kh[base + lane]      = hi; g_Kl[base + lane]      = lo;
        split2(y2 * r, hi, lo); g_Kh[base + lane + 32] = hi; g_Kl[base + lane + 32] = lo;
    }
    {
        float v1 = qkv[1280 + w * HD + lane]      + gate * ve[bt * (NKV * HD) + w * HD + lane];
        float v2 = qkv[1280 + w * HD + 32 + lane] + gate * ve[bt * (NKV * HD) + w * HD + 32 + lane];
        size_t base = ((size_t)(b * NKV + w) * TT + t) * HD;
        __nv_bfloat16 hi, lo;
        split2(v1, hi, lo); g_Vh[base + lane]      = hi; g_Vl[base + lane]      = lo;
        split2(v2, hi, lo); g_Vh[base + lane + 32] = hi; g_Vl[base + lane + 32] = lo;
    }
}

// ==== tensor-core flash attention: 128 q-rows/CTA, 8 warps, dbuf K/V ========
#define AP 72
#define AQS (128 * AP)                   // Q array elems
#define AKS (64 * AP)                    // K/V tile array elems
#define ATT_SMEM ((2 * AQS + 8 * AKS) * 2)
// score scale with log2(e) folded in: softmax uses ex2
#define ESC 0.1803368801111204f          // 0.125 * log2(e)

__global__ void __launch_bounds__(256, 2) attn_tc_kernel(const void* __restrict__ winptr)
{
    extern __shared__ __nv_bfloat16 smb[];
    __nv_bfloat16* sQh = smb;
    __nv_bfloat16* sQl = smb + AQS;

    // heavy q-tiles first: better wave packing
    const int q0 = (gridDim.x - 1 - blockIdx.x) * 128;
    const int h  = blockIdx.y;
    const int b  = blockIdx.z;
    const int kh = h >> 2;

    const int tid = threadIdx.x, w = tid >> 5, lane = tid & 31;

    int  wi = *(const int*)winptr;
    float wf = *(const float*)winptr;
    const int W = (wi > 0 && wi < (1 << 20)) ? wi : (int)wf;

    const size_t kvbase = (size_t)(b * NKV + kh) * TT * HD;

    const int kr = tid >> 2, kq = tid & 3;
    const uint32_t ksoff = (uint32_t)(kr * AP + kq * 16) * 2;

    int kbeg = q0 - W; if (kbeg < 0) kbeg = 0;
    const int kstart = (kbeg / 64) * 64;
    const int klast  = q0 + 64;

    auto issue_tile = [&](int k0, int bf) {
        const size_t g = kvbase + (size_t)(k0 + kr) * HD + kq * 16;
        uint32_t base = smem_u32(smb + 2 * AQS + bf * 4 * AKS) + ksoff;
        const __nv_bfloat16* srcs[4] = { g_Kh + g, g_Kl + g, g_Vh + g, g_Vl + g };
        #pragma unroll
        for (int a = 0; a < 4; a++) {
            cpa16(base + a * AKS * 2,      srcs[a]);
            cpa16(base + a * AKS * 2 + 16, srcs[a] + 8);
        }
    };

    {
        const int lr = tid >> 1, lhf = tid & 1;
        size_t gq = ((size_t)(b * NH + h) * TT + q0 + lr) * HD + lhf * 32;
        #pragma unroll
        for (int j = 0; j < 4; j++) {
            *(uint4*)&sQh[lr * AP + lhf * 32 + j * 8] = *(const uint4*)&g_Qh[gq + j * 8];
            *(uint4*)&sQl[lr * AP + lhf * 32 + j * 8] = *(const uint4*)&g_Ql[gq + j * 8];
        }
    }
    issue_tile(kstart, 0);
    CP_COMMIT();
    __syncthreads();

    uint32_t qh[4][4], ql[4][4];
    {
        const int qrow = w * 16 + (lane & 15);
        #pragma unroll
        for (int ks = 0; ks < 4; ks++) {
            int col = ks * 16 + ((lane & 16) ? 8 : 0);
            ldm_x4(smem_u32(&sQh[qrow * AP + col]), qh[ks]);
            ldm_x4(smem_u32(&sQl[qrow * AP + col]), ql[ks]);
        }
    }

    float o[8][4];
    #pragma unroll
    for (int d = 0; d < 8; d++)
        #pragma unroll
        for (int e = 0; e < 4; e++) o[d][e] = 0.f;
    float m_lo = -INFINITY, m_hi = -INFINITY, l_lo = 0.f, l_hi = 0.f;

    const int wmin = q0 + w * 16;
    const int wmax = wmin + 15;
    const int row_lo = wmin + (lane >> 2);
    const int row_hi = row_lo + 8;
    const int colb   = (lane & 3) * 2;

    int buf = 0;
    for (int k0 = kstart; k0 <= klast; k0 += 64) {
        CP_WAIT0();
        __syncthreads();
        if (k0 + 64 <= klast) {
            issue_tile(k0 + 64, buf ^ 1);
            CP_COMMIT();
        }

        const bool active = (k0 <= wmax) && (k0 + 63 >= wmin - W);
        if (active) {
            __nv_bfloat16* sKh = smb + 2 * AQS + buf * 4 * AKS;
            __nv_bfloat16* sKl = sKh + AKS;
            __nv_bfloat16* sVh = sKh + 2 * AKS;
            __nv_bfloat16* sVl = sKh + 3 * AKS;

            float s[8][4];
            #pragma unroll
            for (int nj = 0; nj < 8; nj++)
                #pragma unroll
                for (int e = 0; e < 4; e++) s[nj][e] = 0.f;

            #pragma unroll
            for (int ks = 0; ks < 4; ks++) {
                #pragma unroll
                for (int nt = 0; nt < 4; nt++) {
                    int krow = nt * 16 + ((lane & 16) >> 1) + (lane & 7);
                    int col  = ks * 16 + ((lane & 8) ? 8 : 0);
                    uint32_t rh[4], rl[4];
                    ldm_x4(smem_u32(&sKh[krow * AP + col]), rh);
                    ldm_x4(smem_u32(&sKl[krow * AP + col]), rl);
                    #pragma unroll
                    for (int e = 0; e < 2; e++) {
                        uint32_t bhf[2] = { rh[e*2], rh[e*2+1] };
                        uint32_t blf[2] = { rl[e*2], rl[e*2+1] };
                        mma_bf16(s[nt*2+e], qh[ks], bhf);
                        mma_bf16(s[nt*2+e], ql[ks], bhf);
                        mma_bf16(s[nt*2+e], qh[ks], blf);
                    }
                }
            }

            // mask + scale into log2 domain
            #pragma unroll
            for (int nj = 0; nj < 8; nj++) {
                #pragma unroll
                for (int e = 0; e < 4; e++) {
                    int col = k0 + nj * 8 + colb + (e & 1);
                    int row = (e < 2) ? row_lo : row_hi;
                    bool ok = (col <= row) && (row - col <= W);
                    s[nj][e] = ok ? s[nj][e] * ESC : -3e9f;
                }
            }

            float mx_lo = -INFINITY, mx_hi = -INFINITY;
            #pragma unroll
            for (int nj = 0; nj < 8; nj++) {
                mx_lo = fmaxf(mx_lo, fmaxf(s[nj][0], s[nj][1]));
                mx_hi = fmaxf(mx_hi, fmaxf(s[nj][2], s[nj][3]));
            }
            mx_lo = fmaxf(mx_lo, __shfl_xor_sync(0xffffffffu, mx_lo, 1));
            mx_lo = fmaxf(mx_lo, __shfl_xor_sync(0xffffffffu, mx_lo, 2));
            mx_hi = fmaxf(mx_hi, __shfl_xor_sync(0xffffffffu, mx_hi, 1));
            mx_hi = fmaxf(mx_hi, __shfl_xor_sync(0xffffffffu, mx_hi, 2));

            float mnew_lo = fmaxf(fmaxf(m_lo, mx_lo), -1e9f);
            float mnew_hi = fmaxf(fmaxf(m_hi, mx_hi), -1e9f);
            float sc_lo = ex2(m_lo - mnew_lo);
            float sc_hi = ex2(m_hi - mnew_hi);
            m_lo = mnew_lo; m_hi = mnew_hi;

            float sum_lo = 0.f, sum_hi = 0.f;
            #pragma unroll
            for (int nj = 0; nj < 8; nj++) {
                s[nj][0] = ex2(s[nj][0] - mnew_lo);
                s[nj][1] = ex2(s[nj][1] - mnew_lo);
                s[nj][2] = ex2(s[nj][2] - mnew_hi);
                s[nj][3] = ex2(s[nj][3] - mnew_hi);
                sum_lo += s[nj][0] + s[nj][1];
                sum_hi += s[nj][2] + s[nj][3];
            }
            sum_lo += __shfl_xor_sync(0xffffffffu, sum_lo, 1);
            sum_lo += __shfl_xor_sync(0xffffffffu, sum_lo, 2);
            sum_hi += __shfl_xor_sync(0xffffffffu, sum_hi, 1);
            sum_hi += __shfl_xor_sync(0xffffffffu, sum_hi, 2);
            l_lo = l_lo * sc_lo + sum_lo;
            l_hi = l_hi * sc_hi + sum_hi;

            #pragma unroll
            for (int d = 0; d < 8; d++) {
                o[d][0] *= sc_lo; o[d][1] *= sc_lo;
                o[d][2] *= sc_hi; o[d][3] *= sc_hi;
            }

            // ---- O += P V; P packed per-ks to cut register pressure ----
            #pragma unroll
            for (int ks = 0; ks < 4; ks++) {
                uint32_t ph[4], pl[4];
                #pragma unroll
                for (int e = 0; e < 2; e++) {
                    int nj = ks * 2 + e;
                    float p0 = s[nj][0], p1 = s[nj][1], p2 = s[nj][2], p3 = s[nj][3];
                    uint32_t h01 = packbf(p0, p1);
                    uint32_t h23 = packbf(p2, p3);
                    __nv_bfloat162 hb01 = *(__nv_bfloat162*)&h01;
                    __nv_bfloat162 hb23 = *(__nv_bfloat162*)&h23;
                    pl[e*2]   = packbf(p0 - __bfloat162float(hb01.x),
                                       p1 - __bfloat162float(hb01.y));
                    pl[e*2+1] = packbf(p2 - __bfloat162float(hb23.x),
                                       p3 - __bfloat162float(hb23.y));
                    ph[e*2]   = h01; ph[e*2+1] = h23;
                }
                #pragma unroll
                for (int dt = 0; dt < 4; dt++) {
                    int vrow = ks * 16 + (lane & 15);
                    int vcol = dt * 16 + ((lane & 16) ? 8 : 0);
                    uint32_t rh[4], rl[4];
                    ldm_x4t(smem_u32(&sVh[vrow * AP + vcol]), rh);
                    ldm_x4t(smem_u32(&sVl[vrow * AP + vcol]), rl);
                    #pragma unroll
                    for (int e = 0; e < 2; e++) {
                        uint32_t bhf[2] = { rh[e*2], rh[e*2+1] };
                        uint32_t blf[2] = { rl[e*2], rl[e*2+1] };
                        mma_bf16(o[dt*2+e], ph, bhf);
                        mma_bf16(o[dt*2+e], pl, bhf);
                        mma_bf16(o[dt*2+e], ph, blf);
                    }
                }
            }
        }
        buf ^= 1;
    }

    float li_lo = 1.f / l_lo, li_hi = 1.f / l_hi;
    #pragma unroll
    for (int d = 0; d < 8; d++) {
        int col = h * HD + d * 8 + colb;
        *(float2*)&g_Y[(size_t)(b * TT + row_lo) * CC + col] =
            make_float2(o[d][0] * li_lo, o[d][1] * li_lo);
        *(float2*)&g_Y[(size_t)(b * TT + row_hi) * CC + col] =
            make_float2(o[d][2] * li_hi, o[d][3] * li_hi);
    }
}

// ---------------------------------------------------------------------------
extern "C" void kernel_launch(void* const* d_in, const int* in_sizes, int n_in,
                              void* d_out, int out_size)
{
    const float* x    = (const float*)d_in[0];
    const float* ve   = (const float*)d_in[1];
    const float* cosb = (const float*)d_in[2];
    const float* sinb = (const float*)d_in[3];
    const float* Wq   = (const float*)d_in[4];
    const float* Wk   = (const float*)d_in[5];
    const float* Wv   = (const float*)d_in[6];
    const float* Wp   = (const float*)d_in[7];
    const float* Wg   = (const float*)d_in[8];
    const void*  win  = d_in[9];
    float* out = (float*)d_out;

    cudaFuncSetAttribute(attn_tc_kernel, cudaFuncAttributeMaxDynamicSharedMemorySize,
                         ATT_SMEM);
    cudaFuncSetAttribute(tc_gemm, cudaFuncAttributeMaxDynamicSharedMemorySize,
                         GEMM_SMEM);

    __nv_bfloat16 *wh, *wl, *ph, *pl;
    cudaGetSymbolAddress((void**)&wh, g_wh);
    cudaGetSymbolAddress((void**)&wl, g_wl);
    cudaGetSymbolAddress((void**)&ph, g_ph);
    cudaGetSymbolAddress((void**)&pl, g_pl);
    float *qkvp, *Yp;
    cudaGetSymbolAddress((void**)&qkvp, g_qkv);
    cudaGetSymbolAddress((void**)&Yp, g_Y);

    // all weight transposes in ONE launch
    wtrans_all_kernel<<<dim3(32, 32, 4), 256>>>(Wq, Wk, Wv, Wp, wh, wl, ph, pl);

    // qkv = x @ [Wq|Wk|Wv]
    tc_gemm<<<dim3(12, 32), 256, GEMM_SMEM>>>(x, wh, wl, qkvp, 1024, QKVN);

    pointwise_kernel<<<MTOT, 128>>>(x, ve, cosb, sinb, Wg);

    attn_tc_kernel<<<dim3(TT / 128, NH, BB), 256, ATT_SMEM>>>(win);

    // out = Y @ Wproj
    tc_gemm<<<dim3(8, 32), 256, GEMM_SMEM>>>(Yp, ph, pl, out, 1024, 1024);
}

// round 14
// speedup vs baseline: 1.8205x; 1.1828x over previous
#include <cuda_runtime.h>
#include <cuda_bf16.h>
#include <cuda_fp16.h>
#include <math.h>
#include <stdint.h>

// Problem constants
#define BB   2
#define TT   2048
#define CC   1024
#define NH   16
#define NKV  4
#define HD   64
#define MTOT (BB*TT)          // 4096
#define QKVN 1536             // 1024 + 256 + 256

// ---------------- scratch (device globals; no allocation allowed) ----------
__device__ float g_qkv[MTOT * QKVN];          // x @ [Wq|Wk|Wv] (fp32)
__device__ float g_Y[MTOT * CC];              // attention output [b,t,h,d]
// fp16 Q (split hi/lo) and K/V (single), [b,h,t,d] layout
__device__ __half g_Qh[BB * NH  * TT * HD];
__device__ __half g_Ql[BB * NH  * TT * HD];
__device__ __half g_Kf[BB * NKV * TT * HD];
__device__ __half g_Vf[BB * NKV * TT * HD];
// transposed + bf16-split weights: Wt[n][k] (K-major, K=1024)
__device__ __nv_bfloat16 g_wh[QKVN * CC];
__device__ __nv_bfloat16 g_wl[QKVN * CC];
__device__ __nv_bfloat16 g_ph[CC * CC];
__device__ __nv_bfloat16 g_pl[CC * CC];

// ---------------------------------------------------------------------------
__device__ __forceinline__ uint32_t smem_u32(const void* p) {
    uint32_t a;
    asm("{ .reg .u64 t; cvta.to.shared.u64 t, %1; cvt.u32.u64 %0, t; }"
        : "=r"(a) : "l"(p));
    return a;
}

__device__ __forceinline__ void split2(float v, __nv_bfloat16& hi, __nv_bfloat16& lo) {
    hi = __float2bfloat16(v);
    lo = __float2bfloat16(v - __bfloat162float(hi));
}
__device__ __forceinline__ void split2h(float v, __half& hi, __half& lo) {
    hi = __float2half(v);
    lo = __float2half(v - __half2float(hi));
}

__device__ __forceinline__ void ldm_x4(uint32_t addr, uint32_t r[4]) {
    asm volatile("ldmatrix.sync.aligned.m8n8.x4.shared.b16 {%0,%1,%2,%3}, [%4];"
        : "=r"(r[0]), "=r"(r[1]), "=r"(r[2]), "=r"(r[3]) : "r"(addr));
}
__device__ __forceinline__ void ldm_x4t(uint32_t addr, uint32_t r[4]) {
    asm volatile("ldmatrix.sync.aligned.m8n8.x4.trans.shared.b16 {%0,%1,%2,%3}, [%4];"
        : "=r"(r[0]), "=r"(r[1]), "=r"(r[2]), "=r"(r[3]) : "r"(addr));
}

__device__ __forceinline__ void mma_bf16(float d[4], const uint32_t a[4],
                                         const uint32_t b[2]) {
    asm volatile(
        "mma.sync.aligned.m16n8k16.row.col.f32.bf16.bf16.f32 "
        "{%0,%1,%2,%3}, {%4,%5,%6,%7}, {%8,%9}, {%0,%1,%2,%3};"
        : "+f"(d[0]), "+f"(d[1]), "+f"(d[2]), "+f"(d[3])
        : "r"(a[0]), "r"(a[1]), "r"(a[2]), "r"(a[3]), "r"(b[0]), "r"(b[1]));
}
__device__ __forceinline__ void mma_f16(float d[4], const uint32_t a[4],
                                        const uint32_t b[2]) {
    asm volatile(
        "mma.sync.aligned.m16n8k16.row.col.f32.f16.f16.f32 "
        "{%0,%1,%2,%3}, {%4,%5,%6,%7}, {%8,%9}, {%0,%1,%2,%3};"
        : "+f"(d[0]), "+f"(d[1]), "+f"(d[2]), "+f"(d[3])
        : "r"(a[0]), "r"(a[1]), "r"(a[2]), "r"(a[3]), "r"(b[0]), "r"(b[1]));
}

__device__ __forceinline__ uint32_t packh(float e0, float e1) {
    uint32_t r;
    asm("cvt.rn.f16x2.f32 %0, %1, %2;" : "=r"(r) : "f"(e1), "f"(e0));
    return r;
}

// fast exp2: single MUFU.EX2 (exp2f without fast-math is a slow softpath!)
__device__ __forceinline__ float ex2(float x) {
    float y;
    asm("ex2.approx.ftz.f32 %0, %1;" : "=f"(y) : "f"(x));
    return y;
}

__device__ __forceinline__ void cpa16(uint32_t s, const void* g) {
    asm volatile("cp.async.cg.shared.global [%0], [%1], 16;" :: "r"(s), "l"(g));
}
#define CP_COMMIT() asm volatile("cp.async.commit_group;" ::: "memory")
#define CP_WAIT0()  asm volatile("cp.async.wait_group 0;" ::: "memory")

// ==== merged weight transpose + bf16 split (all 4 matrices, one launch) =====
__global__ void __launch_bounds__(256) wtrans_all_kernel(
    const float* __restrict__ Wq, const float* __restrict__ Wk,
    const float* __restrict__ Wv, const float* __restrict__ Wp,
    __nv_bfloat16* __restrict__ wh, __nv_bfloat16* __restrict__ wl,
    __nv_bfloat16* __restrict__ ph, __nv_bfloat16* __restrict__ pl)
{
    const int z = blockIdx.z;
    const float* src; int N, n0out;
    __nv_bfloat16 *dh, *dl;
    if (z == 0)      { src = Wq; N = 1024; n0out = 0;    dh = wh; dl = wl; }
    else if (z == 1) { src = Wk; N = 256;  n0out = 1024; dh = wh; dl = wl; }
    else if (z == 2) { src = Wv; N = 256;  n0out = 1280; dh = wh; dl = wl; }
    else             { src = Wp; N = 1024; n0out = 0;    dh = ph; dl = pl; }
    if (blockIdx.x * 32 >= N) return;

    __shared__ float t[32][33];
    const int tx = threadIdx.x & 31, ty = threadIdx.x >> 5;
    const int k0 = blockIdx.y * 32, nb = blockIdx.x * 32;
    #pragma unroll
    for (int i = 0; i < 4; i++)
        t[ty + 8 * i][tx] = src[(size_t)(k0 + ty + 8 * i) * N + nb + tx];
    __syncthreads();
    #pragma unroll
    for (int i = 0; i < 4; i++) {
        int nl = ty + 8 * i;
        float v = t[tx][nl];
        __nv_bfloat16 hi, lo; split2(v, hi, lo);
        size_t idx = (size_t)(n0out + nb + nl) * 1024 + k0 + tx;
        dh[idx] = hi; dl[idx] = lo;
    }
}

// ==== split-bf16 mma.sync GEMM, double-buffered (cp.async B, reg-prefetch A)
#define SP 40
#define TS (128 * SP)
#define GEMM_SMEM (8 * TS * 2)

__global__ void __launch_bounds__(256, 2)
tc_gemm(const float* __restrict__ A,
        const __nv_bfloat16* __restrict__ Bh, const __nv_bfloat16* __restrict__ Bl,
        float* __restrict__ C, int K, int ldc)
{
    extern __shared__ __nv_bfloat16 gsm[];

    const int tid  = threadIdx.x;
    const int wid  = tid >> 5;
    const int lane = tid & 31;
    const int m0 = blockIdx.y * 128;
    const int n0 = blockIdx.x * 128;
    const int warp_m = wid & 1;
    const int warp_n = wid >> 1;

    float acc[4][4][4];
    #pragma unroll
    for (int i = 0; i < 4; i++)
        #pragma unroll
        for (int j = 0; j < 4; j++)
            #pragma unroll
            for (int f = 0; f < 4; f++) acc[i][j][f] = 0.f;

    const int lr = tid >> 1;
    const int lh = tid & 1;
    const int soff = lr * SP + lh * 16;

    const float* gA = A + (size_t)(m0 + lr) * K + lh * 16;
    const __nv_bfloat16* gbh = Bh + (size_t)(n0 + lr) * K + lh * 16;
    const __nv_bfloat16* gbl = Bl + (size_t)(n0 + lr) * K + lh * 16;

    const int a_row = warp_m * 64 + (lane & 15);
    const int a_koff = (lane & 16) ? 8 : 0;
    const int b_rowbase = warp_n * 32 + ((lane & 16) >> 1) + (lane & 7);
    const int b_koff = (lane & 8) ? 8 : 0;

    const int nb = K >> 5;

    {
        __nv_bfloat16* bAh = gsm;
        __nv_bfloat16* bAl = gsm + TS;
        #pragma unroll
        for (int j = 0; j < 4; j++) {
            float4 v = *(const float4*)(gA + j * 4);
            __align__(8) __nv_bfloat16 hb[4], lb[4];
            split2(v.x, hb[0], lb[0]); split2(v.y, hb[1], lb[1]);
            split2(v.z, hb[2], lb[2]); split2(v.w, hb[3], lb[3]);
            *(uint2*)(bAh + soff + j * 4) = *(uint2*)hb;
            *(uint2*)(bAl + soff + j * 4) = *(uint2*)lb;
        }
        uint32_t sbh = smem_u32(gsm + 2 * TS + soff);
        uint32_t sbl = smem_u32(gsm + 3 * TS + soff);
        cpa16(sbh,      gbh);     cpa16(sbh + 16, gbh + 8);
        cpa16(sbl,      gbl);     cpa16(sbl + 16, gbl + 8);
        CP_COMMIT();
    }
    CP_WAIT0();
    __syncthreads();

    for (int c = 0; c < nb; c++) {
        const int buf = c & 1;
        __nv_bfloat16* sAh = gsm + buf * 4 * TS;
        __nv_bfloat16* sAl = sAh + TS;
        __nv_bfloat16* sBh = sAh + 2 * TS;
        __nv_bfloat16* sBl = sAh + 3 * TS;
        __nv_bfloat16* nAh = gsm + (buf ^ 1) * 4 * TS;
        __nv_bfloat16* nAl = nAh + TS;

        float4 av[4];
        const bool more = (c + 1 < nb);
        if (more) {
            const int kc = (c + 1) << 5;
            #pragma unroll
            for (int j = 0; j < 4; j++) av[j] = *(const float4*)(gA + kc + j * 4);
            uint32_t sbh = smem_u32(nAh + 2 * TS + soff);
            uint32_t sbl = smem_u32(nAh + 3 * TS + soff);
            cpa16(sbh,      gbh + kc);     cpa16(sbh + 16, gbh + kc + 8);
            cpa16(sbl,      gbl + kc);     cpa16(sbl + 16, gbl + kc + 8);
            CP_COMMIT();
        }

        #pragma unroll
        for (int kk = 0; kk < 32; kk += 16) {
            uint32_t bh[4][2], bl[4][2];
            #pragma unroll
            for (int p = 0; p < 2; p++) {
                uint32_t r[4];
                uint32_t ad = smem_u32(&sBh[(b_rowbase + p * 16) * SP + kk + b_koff]);
                ldm_x4(ad, r);
                bh[p*2][0] = r[0]; bh[p*2][1] = r[1];
                bh[p*2+1][0] = r[2]; bh[p*2+1][1] = r[3];
                ad = smem_u32(&sBl[(b_rowbase + p * 16) * SP + kk + b_koff]);
                ldm_x4(ad, r);
                bl[p*2][0] = r[0]; bl[p*2][1] = r[1];
                bl[p*2+1][0] = r[2]; bl[p*2+1][1] = r[3];
            }
            #pragma unroll
            for (int mi = 0; mi < 4; mi++) {
                uint32_t ah[4], al[4];
                uint32_t ad = smem_u32(&sAh[(a_row + mi * 16) * SP + kk + a_koff]);
                ldm_x4(ad, ah);
                ad = smem_u32(&sAl[(a_row + mi * 16) * SP + kk + a_koff]);
                ldm_x4(ad, al);
                #pragma unroll
                for (int nj = 0; nj < 4; nj++) {
                    mma_bf16(acc[mi][nj], ah, bh[nj]);
                    mma_bf16(acc[mi][nj], ah, bl[nj]);
                    mma_bf16(acc[mi][nj], al, bh[nj]);
                }
            }
        }

        if (more) {
            #pragma unroll
            for (int j = 0; j < 4; j++) {
                __align__(8) __nv_bfloat16 hb[4], lb[4];
                split2(av[j].x, hb[0], lb[0]); split2(av[j].y, hb[1], lb[1]);
                split2(av[j].z, hb[2], lb[2]); split2(av[j].w, hb[3], lb[3]);
                *(uint2*)(nAh + soff + j * 4) = *(uint2*)hb;
                *(uint2*)(nAl + soff + j * 4) = *(uint2*)lb;
            }
        }
        CP_WAIT0();
        __syncthreads();
    }

    const int gid = lane >> 2, tig = lane & 3;
    #pragma unroll
    for (int mi = 0; mi < 4; mi++) {
        int row = m0 + warp_m * 64 + mi * 16 + gid;
        #pragma unroll
        for (int nj = 0; nj < 4; nj++) {
            int col = n0 + warp_n * 32 + nj * 8 + tig * 2;
            *(float2*)&C[(size_t)row * ldc + col] =
                make_float2(acc[mi][nj][0], acc[mi][nj][1]);
            *(float2*)&C[(size_t)(row + 8) * ldc + col] =
                make_float2(acc[mi][nj][2], acc[mi][nj][3]);
        }
    }
}

// ---- pointwise: gate + ve, RoPE, RMSNorm*1.2; Q fp16-split, K/V fp16 ------
__global__ void __launch_bounds__(128) pointwise_kernel(
    const float* __restrict__ x,
    const float* __restrict__ ve,
    const float* __restrict__ cosb,
    const float* __restrict__ sinb,
    const float* __restrict__ Wg)
{
    const int bt   = blockIdx.x;
    const int b    = bt >> 11;
    const int t    = bt & (TT - 1);
    const int tid  = threadIdx.x;
    const int w    = tid >> 5;
    const int lane = tid & 31;

    float p = (lane < 12) ? x[bt * CC + lane] * Wg[lane * NKV + w] : 0.f;
    #pragma unroll
    for (int o = 16; o; o >>= 1) p += __shfl_xor_sync(0xffffffffu, p, o);
    const float gate = 3.f / (1.f + __expf(-p));

    const float c = cosb[t * 32 + lane];
    const float s = sinb[t * 32 + lane];
    const float* qkv = &g_qkv[bt * QKVN];

    for (int h = w; h < NH; h += 4) {
        float x1 = qkv[h * HD + lane];
        float x2 = qkv[h * HD + 32 + lane];
        float y1 =  x1 * c + x2 * s;
        float y2 = -x1 * s + x2 * c;
        float ss = y1 * y1 + y2 * y2;
        #pragma unroll
        for (int o = 16; o; o >>= 1) ss += __shfl_xor_sync(0xffffffffu, ss, o);
        float r = rsqrtf(ss * (1.f / 64.f) + 1e-6f) * 1.2f;
        size_t base = ((size_t)(b * NH + h) * TT + t) * HD;
        __half hi, lo;
        split2h(y1 * r, hi, lo); g_Qh[base + lane]      = hi; g_Ql[base + lane]      = lo;
        split2h(y2 * r, hi, lo); g_Qh[base + lane + 32] = hi; g_Ql[base + lane + 32] = lo;
    }
    {
        float x1 = qkv[1024 + w * HD + lane];
        float x2 = qkv[1024 + w * HD + 32 + lane];
        float y1 =  x1 * c + x2 * s;
        float y2 = -x1 * s + x2 * c;
        float ss = y1 * y1 + y2 * y2;
        #pragma unroll
        for (int o = 16; o; o >>= 1) ss += __shfl_xor_sync(0xffffffffu, ss, o);
        float r = rsqrtf(ss * (1.f / 64.f) + 1e-6f) * 1.2f;
        size_t base = ((size_t)(b * NKV + w) * TT + t) * HD;
        g_Kf[base + lane]      = __float2half(y1 * r);
        g_Kf[base + lane + 32] = __float2half(y2 * r);
    }
    {
        float v1 = qkv[1280 + w * HD + lane]      + gate * ve[bt * (NKV * HD) + w * HD + lane];
        float v2 = qkv[1280 + w * HD + 32 + lane] + gate * ve[bt * (NKV * HD) + w * HD + 32 + lane];
        size_t base = ((size_t)(b * NKV + w) * TT + t) * HD;
        g_Vf[base + lane]      = __float2half(v1);
        g_Vf[base + lane + 32] = __float2half(v2);
    }
}

// ==== fp16 tensor-core flash attention: 128 q-rows/CTA, 8 warps, dbuf K/V ===
#define AP 72
#define AQS (128 * AP)                   // Q array elems
#define AKS (64 * AP)                    // K/V tile array elems
#define ATT_SMEM ((2 * AQS + 4 * AKS) * 2)   // Qh Ql + 2 x (K V)
// score scale with log2(e) folded in: softmax uses ex2
#define ESC 0.1803368801111204f          // 0.125 * log2(e)

__global__ void __launch_bounds__(256, 2) attn_tc_kernel(const void* __restrict__ winptr)
{
    extern __shared__ __half smh[];
    __half* sQh = smh;
    __half* sQl = smh + AQS;

    // heavy q-tiles first: better wave packing
    const int q0 = (gridDim.x - 1 - blockIdx.x) * 128;
    const int h  = blockIdx.y;
    const int b  = blockIdx.z;
    const int kh = h >> 2;

    const int tid = threadIdx.x, w = tid >> 5, lane = tid & 31;

    int  wi = *(const int*)winptr;
    float wf = *(const float*)winptr;
    const int W = (wi > 0 && wi < (1 << 20)) ? wi : (int)wf;

    const size_t kvbase = (size_t)(b * NKV + kh) * TT * HD;

    const int kr = tid >> 2, kq = tid & 3;
    const uint32_t ksoff = (uint32_t)(kr * AP + kq * 16) * 2;

    int kbeg = q0 - W; if (kbeg < 0) kbeg = 0;
    const int kstart = (kbeg / 64) * 64;
    const int klast  = q0 + 64;

    auto issue_tile = [&](int k0, int bf) {
        const size_t g = kvbase + (size_t)(k0 + kr) * HD + kq * 16;
        uint32_t base = smem_u32(smh + 2 * AQS + bf * 2 * AKS) + ksoff;
        cpa16(base,                g_Kf + g);
        cpa16(base + 16,           g_Kf + g + 8);
        cpa16(base + AKS * 2,      g_Vf + g);
        cpa16(base + AKS * 2 + 16, g_Vf + g + 8);
    };

    {
        const int lr = tid >> 1, lhf = tid & 1;
        size_t gq = ((size_t)(b * NH + h) * TT + q0 + lr) * HD + lhf * 32;
        #pragma unroll
        for (int j = 0; j < 4; j++) {
            *(uint4*)&sQh[lr * AP + lhf * 32 + j * 8] = *(const uint4*)&g_Qh[gq + j * 8];
            *(uint4*)&sQl[lr * AP + lhf * 32 + j * 8] = *(const uint4*)&g_Ql[gq + j * 8];
        }
    }
    issue_tile(kstart, 0);
    CP_COMMIT();
    __syncthreads();

    uint32_t qh[4][4], ql[4][4];
    {
        const int qrow = w * 16 + (lane & 15);
        #pragma unroll
        for (int ks = 0; ks < 4; ks++) {
            int col = ks * 16 + ((lane & 16) ? 8 : 0);
            ldm_x4(smem_u32(&sQh[qrow * AP + col]), qh[ks]);
            ldm_x4(smem_u32(&sQl[qrow * AP + col]), ql[ks]);
        }
    }

    float o[8][4];
    #pragma unroll
    for (int d = 0; d < 8; d++)
        #pragma unroll
        for (int e = 0; e < 4; e++) o[d][e] = 0.f;
    float m_lo = -INFINITY, m_hi = -INFINITY, l_lo = 0.f, l_hi = 0.f;

    const int wmin = q0 + w * 16;
    const int wmax = wmin + 15;
    const int row_lo = wmin + (lane >> 2);
    const int row_hi = row_lo + 8;
    const int colb   = (lane & 3) * 2;

    int buf = 0;
    for (int k0 = kstart; k0 <= klast; k0 += 64) {
        CP_WAIT0();
        __syncthreads();
        if (k0 + 64 <= klast) {
            issue_tile(k0 + 64, buf ^ 1);
            CP_COMMIT();
        }

        const bool active = (k0 <= wmax) && (k0 + 63 >= wmin - W);
        if (active) {
            __half* sK = smh + 2 * AQS + buf * 2 * AKS;
            __half* sV = sK + AKS;

            // ---- S = Q K^T (fp16: Qhi + Qlo, K single) ----
            float s[8][4];
            #pragma unroll
            for (int nj = 0; nj < 8; nj++)
                #pragma unroll
                for (int e = 0; e < 4; e++) s[nj][e] = 0.f;

            #pragma unroll
            for (int ks = 0; ks < 4; ks++) {
                #pragma unroll
                for (int nt = 0; nt < 4; nt++) {
                    int krow = nt * 16 + ((lane & 16) >> 1) + (lane & 7);
                    int col  = ks * 16 + ((lane & 8) ? 8 : 0);
                    uint32_t rk[4];
                    ldm_x4(smem_u32(&sK[krow * AP + col]), rk);
                    #pragma unroll
                    for (int e = 0; e < 2; e++) {
                        uint32_t bf[2] = { rk[e*2], rk[e*2+1] };
                        mma_f16(s[nt*2+e], qh[ks], bf);
                        mma_f16(s[nt*2+e], ql[ks], bf);
                    }
                }
            }

            // ---- scale (+ mask only on boundary tiles) ----
            const bool full = (k0 + 63 <= wmin) && (wmax - k0 <= W);
            if (full) {
                #pragma unroll
                for (int nj = 0; nj < 8; nj++)
                    #pragma unroll
                    for (int e = 0; e < 4; e++) s[nj][e] *= ESC;
            } else {
                #pragma unroll
                for (int nj = 0; nj < 8; nj++) {
                    #pragma unroll
                    for (int e = 0; e < 4; e++) {
                        int col = k0 + nj * 8 + colb + (e & 1);
                        int row = (e < 2) ? row_lo : row_hi;
                        bool ok = (col <= row) && (row - col <= W);
                        s[nj][e] = ok ? s[nj][e] * ESC : -3e9f;
                    }
                }
            }

            float mx_lo = -INFINITY, mx_hi = -INFINITY;
            #pragma unroll
            for (int nj = 0; nj < 8; nj++) {
                mx_lo = fmaxf(mx_lo, fmaxf(s[nj][0], s[nj][1]));
                mx_hi = fmaxf(mx_hi, fmaxf(s[nj][2], s[nj][3]));
            }
            mx_lo = fmaxf(mx_lo, __shfl_xor_sync(0xffffffffu, mx_lo, 1));
            mx_lo = fmaxf(mx_lo, __shfl_xor_sync(0xffffffffu, mx_lo, 2));
            mx_hi = fmaxf(mx_hi, __shfl_xor_sync(0xffffffffu, mx_hi, 1));
            mx_hi = fmaxf(mx_hi, __shfl_xor_sync(0xffffffffu, mx_hi, 2));

            float mnew_lo = fmaxf(fmaxf(m_lo, mx_lo), -1e9f);
            float mnew_hi = fmaxf(fmaxf(m_hi, mx_hi), -1e9f);
            float sc_lo = ex2(m_lo - mnew_lo);
            float sc_hi = ex2(m_hi - mnew_hi);
            m_lo = mnew_lo; m_hi = mnew_hi;

            float sum_lo = 0.f, sum_hi = 0.f;
            #pragma unroll
            for (int nj = 0; nj < 8; nj++) {
                s[nj][0] = ex2(s[nj][0] - mnew_lo);
                s[nj][1] = ex2(s[nj][1] - mnew_lo);
                s[nj][2] = ex2(s[nj][2] - mnew_hi);
                s[nj][3] = ex2(s[nj][3] - mnew_hi);
                sum_lo += s[nj][0] + s[nj][1];
                sum_hi += s[nj][2] + s[nj][3];
            }
            sum_lo += __shfl_xor_sync(0xffffffffu, sum_lo, 1);
            sum_lo += __shfl_xor_sync(0xffffffffu, sum_lo, 2);
            sum_hi += __shfl_xor_sync(0xffffffffu, sum_hi, 1);
            sum_hi += __shfl_xor_sync(0xffffffffu, sum_hi, 2);
            l_lo = l_lo * sc_lo + sum_lo;
            l_hi = l_hi * sc_hi + sum_hi;

            #pragma unroll
            for (int d = 0; d < 8; d++) {
                o[d][0] *= sc_lo; o[d][1] *= sc_lo;
                o[d][2] *= sc_hi; o[d][3] *= sc_hi;
            }

            // ---- O += P V (P fp16 hi+lo, V single) ----
            #pragma unroll
            for (int ks = 0; ks < 4; ks++) {
                uint32_t ph[4], pl[4];
                #pragma unroll
                for (int e = 0; e < 2; e++) {
                    int nj = ks * 2 + e;
                    float p0 = s[nj][0], p1 = s[nj][1], p2 = s[nj][2], p3 = s[nj][3];
                    uint32_t h01 = packh(p0, p1);
                    uint32_t h23 = packh(p2, p3);
                    __half2 v01 = *(__half2*)&h01;
                    __half2 v23 = *(__half2*)&h23;
                    pl[e*2]   = packh(p0 - __half2float(v01.x),
                                      p1 - __half2float(v01.y));
                    pl[e*2+1] = packh(p2 - __half2float(v23.x),
                                      p3 - __half2float(v23.y));
                    ph[e*2]   = h01; ph[e*2+1] = h23;
                }
                #pragma unroll
                for (int dt = 0; dt < 4; dt++) {
                    int vrow = ks * 16 + (lane & 15);
                    int vcol = dt * 16 + ((lane & 16) ? 8 : 0);
                    uint32_t rv[4];
                    ldm_x4t(smem_u32(&sV[vrow * AP + vcol]), rv);
                    #pragma unroll
                    for (int e = 0; e < 2; e++) {
                        uint32_t bf[2] = { rv[e*2], rv[e*2+1] };
                        mma_f16(o[dt*2+e], ph, bf);
                        mma_f16(o[dt*2+e], pl, bf);
                    }
                }
            }
        }
        buf ^= 1;
    }

    float li_lo = 1.f / l_lo, li_hi = 1.f / l_hi;
    #pragma unroll
    for (int d = 0; d < 8; d++) {
        int col = h * HD + d * 8 + colb;
        *(float2*)&g_Y[(size_t)(b * TT + row_lo) * CC + col] =
            make_float2(o[d][0] * li_lo, o[d][1] * li_lo);
        *(float2*)&g_Y[(size_t)(b * TT + row_hi) * CC + col] =
            make_float2(o[d][2] * li_hi, o[d][3] * li_hi);
    }
}

// ---------------------------------------------------------------------------
extern "C" void kernel_launch(void* const* d_in, const int* in_sizes, int n_in,
                              void* d_out, int out_size)
{
    const float* x    = (const float*)d_in[0];
    const float* ve   = (const float*)d_in[1];
    const float* cosb = (const float*)d_in[2];
    const float* sinb = (const float*)d_in[3];
    const float* Wq   = (const float*)d_in[4];
    const float* Wk   = (const float*)d_in[5];
    const float* Wv   = (const float*)d_in[6];
    const float* Wp   = (const float*)d_in[7];
    const float* Wg   = (const float*)d_in[8];
    const void*  win  = d_in[9];
    float* out = (float*)d_out;

    cudaFuncSetAttribute(attn_tc_kernel, cudaFuncAttributeMaxDynamicSharedMemorySize,
                         ATT_SMEM);
    cudaFuncSetAttribute(tc_gemm, cudaFuncAttributeMaxDynamicSharedMemorySize,
                         GEMM_SMEM);

    __nv_bfloat16 *wh, *wl, *ph, *pl;
    cudaGetSymbolAddress((void**)&wh, g_wh);
    cudaGetSymbolAddress((void**)&wl, g_wl);
    cudaGetSymbolAddress((void**)&ph, g_ph);
    cudaGetSymbolAddress((void**)&pl, g_pl);
    float *qkvp, *Yp;
    cudaGetSymbolAddress((void**)&qkvp, g_qkv);
    cudaGetSymbolAddress((void**)&Yp, g_Y);

    // all weight transposes in ONE launch
    wtrans_all_kernel<<<dim3(32, 32, 4), 256>>>(Wq, Wk, Wv, Wp, wh, wl, ph, pl);

    // qkv = x @ [Wq|Wk|Wv]
    tc_gemm<<<dim3(12, 32), 256, GEMM_SMEM>>>(x, wh, wl, qkvp, 1024, QKVN);

    pointwise_kernel<<<MTOT, 128>>>(x, ve, cosb, sinb, Wg);

    attn_tc_kernel<<<dim3(TT / 128, NH, BB), 256, ATT_SMEM>>>(win);

    // out = Y @ Wproj
    tc_gemm<<<dim3(8, 32), 256, GEMM_SMEM>>>(Yp, ph, pl, out, 1024, 1024);
}

// round 17
// speedup vs baseline: 2.2520x; 1.2371x over previous
#include <cuda_runtime.h>
#include <cuda_bf16.h>
#include <cuda_fp16.h>
#include <math.h>
#include <stdint.h>

// Problem constants
#define BB   2
#define TT   2048
#define CC   1024
#define NH   16
#define NKV  4
#define HD   64
#define MTOT (BB*TT)          // 4096
#define QKVN 1536             // 1024 + 256 + 256

// ---------------- scratch (device globals; no allocation allowed) ----------
__device__ float g_qkv[MTOT * QKVN];          // x @ [Wq|Wk|Wv] (fp32)
__device__ float g_Y[MTOT * CC];              // attention output [b,t,h,d]
// fp16 Q (split hi/lo) and K/V (single), [b,h,t,d] layout
__device__ __half g_Qh[BB * NH  * TT * HD];
__device__ __half g_Ql[BB * NH  * TT * HD];
__device__ __half g_Kf[BB * NKV * TT * HD];
__device__ __half g_Vf[BB * NKV * TT * HD];
// transposed fp16 weights: Wt[n][k] (K-major, K=1024)
__device__ __half g_wf[QKVN * CC];
__device__ __half g_pf[CC * CC];

// ---------------------------------------------------------------------------
__device__ __forceinline__ uint32_t smem_u32(const void* p) {
    uint32_t a;
    asm("{ .reg .u64 t; cvta.to.shared.u64 t, %1; cvt.u32.u64 %0, t; }"
        : "=r"(a) : "l"(p));
    return a;
}

__device__ __forceinline__ void split2h(float v, __half& hi, __half& lo) {
    hi = __float2half(v);
    lo = __float2half(v - __half2float(hi));
}

__device__ __forceinline__ void ldm_x4(uint32_t addr, uint32_t r[4]) {
    asm volatile("ldmatrix.sync.aligned.m8n8.x4.shared.b16 {%0,%1,%2,%3}, [%4];"
        : "=r"(r[0]), "=r"(r[1]), "=r"(r[2]), "=r"(r[3]) : "r"(addr));
}
__device__ __forceinline__ void ldm_x4t(uint32_t addr, uint32_t r[4]) {
    asm volatile("ldmatrix.sync.aligned.m8n8.x4.trans.shared.b16 {%0,%1,%2,%3}, [%4];"
        : "=r"(r[0]), "=r"(r[1]), "=r"(r[2]), "=r"(r[3]) : "r"(addr));
}

__device__ __forceinline__ void mma_f16(float d[4], const uint32_t a[4],
                                        const uint32_t b[2]) {
    asm volatile(
        "mma.sync.aligned.m16n8k16.row.col.f32.f16.f16.f32 "
        "{%0,%1,%2,%3}, {%4,%5,%6,%7}, {%8,%9}, {%0,%1,%2,%3};"
        : "+f"(d[0]), "+f"(d[1]), "+f"(d[2]), "+f"(d[3])
        : "r"(a[0]), "r"(a[1]), "r"(a[2]), "r"(a[3]), "r"(b[0]), "r"(b[1]));
}

__device__ __forceinline__ uint32_t packh(float e0, float e1) {
    uint32_t r;
    asm("cvt.rn.f16x2.f32 %0, %1, %2;" : "=r"(r) : "f"(e1), "f"(e0));
    return r;
}

// fast exp2: single MUFU.EX2
__device__ __forceinline__ float ex2(float x) {
    float y;
    asm("ex2.approx.ftz.f32 %0, %1;" : "=f"(y) : "f"(x));
    return y;
}

__device__ __forceinline__ void cpa16(uint32_t s, const void* g) {
    asm volatile("cp.async.cg.shared.global [%0], [%1], 16;" :: "r"(s), "l"(g));
}
#define CP_COMMIT() asm volatile("cp.async.commit_group;" ::: "memory")
#define CP_WAIT0()  asm volatile("cp.async.wait_group 0;" ::: "memory")

// ==== merged weight transpose -> fp16 (all 4 matrices, one launch) ==========
__global__ void __launch_bounds__(256) wtrans_all_kernel(
    const float* __restrict__ Wq, const float* __restrict__ Wk,
    const float* __restrict__ Wv, const float* __restrict__ Wp,
    __half* __restrict__ wf, __half* __restrict__ pf)
{
    const int z = blockIdx.z;
    const float* src; int N, n0out;
    __half* dst;
    if (z == 0)      { src = Wq; N = 1024; n0out = 0;    dst = wf; }
    else if (z == 1) { src = Wk; N = 256;  n0out = 1024; dst = wf; }
    else if (z == 2) { src = Wv; N = 256;  n0out = 1280; dst = wf; }
    else             { src = Wp; N = 1024; n0out = 0;    dst = pf; }
    if (blockIdx.x * 32 >= N) return;

    __shared__ float t[32][33];
    const int tx = threadIdx.x & 31, ty = threadIdx.x >> 5;
    const int k0 = blockIdx.y * 32, nb = blockIdx.x * 32;
    #pragma unroll
    for (int i = 0; i < 4; i++)
        t[ty + 8 * i][tx] = src[(size_t)(k0 + ty + 8 * i) * N + nb + tx];
    __syncthreads();
    #pragma unroll
    for (int i = 0; i < 4; i++) {
        int nl = ty + 8 * i;
        dst[(size_t)(n0out + nb + nl) * 1024 + k0 + tx] = __float2half(t[tx][nl]);
    }
}

// ==== fp16 mma.sync GEMM (A split hi/lo, B single), double-buffered =========
#define SP 40
#define TS (128 * SP)
#define GEMM_SMEM (6 * TS * 2)           // 2 buffers x (Ah, Al, B)

__global__ void __launch_bounds__(256, 2)
tc_gemm(const float* __restrict__ A, const __half* __restrict__ Bf,
        float* __restrict__ C, int K, int ldc)
{
    extern __shared__ __half gsm[];

    const int tid  = threadIdx.x;
    const int wid  = tid >> 5;
    const int lane = tid & 31;
    const int m0 = blockIdx.y * 128;
    const int n0 = blockIdx.x * 128;
    const int warp_m = wid & 1;
    const int warp_n = wid >> 1;

    float acc[4][4][4];
    #pragma unroll
    for (int i = 0; i < 4; i++)
        #pragma unroll
        for (int j = 0; j < 4; j++)
            #pragma unroll
            for (int f = 0; f < 4; f++) acc[i][j][f] = 0.f;

    const int lr = tid >> 1;
    const int lh = tid & 1;
    const int soff = lr * SP + lh * 16;

    const float* gA = A + (size_t)(m0 + lr) * K + lh * 16;
    const __half* gB = Bf + (size_t)(n0 + lr) * K + lh * 16;

    const int a_row = warp_m * 64 + (lane & 15);
    const int a_koff = (lane & 16) ? 8 : 0;
    const int b_rowbase = warp_n * 32 + ((lane & 16) >> 1) + (lane & 7);
    const int b_koff = (lane & 8) ? 8 : 0;

    const int nb = K >> 5;

    {   // prologue: chunk 0 into buffer 0
        __half* bAh = gsm;
        __half* bAl = gsm + TS;
        #pragma unroll
        for (int j = 0; j < 4; j++) {
            float4 v = *(const float4*)(gA + j * 4);
            __align__(8) __half hb[4], lb[4];
            split2h(v.x, hb[0], lb[0]); split2h(v.y, hb[1], lb[1]);
            split2h(v.z, hb[2], lb[2]); split2h(v.w, hb[3], lb[3]);
            *(uint2*)(bAh + soff + j * 4) = *(uint2*)hb;
            *(uint2*)(bAl + soff + j * 4) = *(uint2*)lb;
        }
        uint32_t sb = smem_u32(gsm + 2 * TS + soff);
        cpa16(sb, gB);  cpa16(sb + 16, gB + 8);
        CP_COMMIT();
    }
    CP_WAIT0();
    __syncthreads();

    for (int c = 0; c < nb; c++) {
        const int buf = c & 1;
        __half* sAh = gsm + buf * 3 * TS;
        __half* sAl = sAh + TS;
        __half* sB  = sAh + 2 * TS;
        __half* nAh = gsm + (buf ^ 1) * 3 * TS;
        __half* nAl = nAh + TS;

        float4 av[4];
        const bool more = (c + 1 < nb);
        if (more) {
            const int kc = (c + 1) << 5;
            #pragma unroll
            for (int j = 0; j < 4; j++) av[j] = *(const float4*)(gA + kc + j * 4);
            uint32_t sb = smem_u32(nAh + 2 * TS + soff);
            cpa16(sb, gB + kc);  cpa16(sb + 16, gB + kc + 8);
            CP_COMMIT();
        }

        #pragma unroll
        for (int kk = 0; kk < 32; kk += 16) {
            uint32_t bfr[4][2];
            #pragma unroll
            for (int p = 0; p < 2; p++) {
                uint32_t r[4];
                uint32_t ad = smem_u32(&sB[(b_rowbase + p * 16) * SP + kk + b_koff]);
                ldm_x4(ad, r);
                bfr[p*2][0] = r[0]; bfr[p*2][1] = r[1];
                bfr[p*2+1][0] = r[2]; bfr[p*2+1][1] = r[3];
            }
            #pragma unroll
            for (int mi = 0; mi < 4; mi++) {
                uint32_t ah[4], al[4];
                uint32_t ad = smem_u32(&sAh[(a_row + mi * 16) * SP + kk + a_koff]);
                ldm_x4(ad, ah);
                ad = smem_u32(&sAl[(a_row + mi * 16) * SP + kk + a_koff]);
                ldm_x4(ad, al);
                #pragma unroll
                for (int nj = 0; nj < 4; nj++) {
                    mma_f16(acc[mi][nj], ah, bfr[nj]);
                    mma_f16(acc[mi][nj], al, bfr[nj]);
                }
            }
        }

        if (more) {
            #pragma unroll
            for (int j = 0; j < 4; j++) {
                __align__(8) __half hb[4], lb[4];
                split2h(av[j].x, hb[0], lb[0]); split2h(av[j].y, hb[1], lb[1]);
                split2h(av[j].z, hb[2], lb[2]); split2h(av[j].w, hb[3], lb[3]);
                *(uint2*)(nAh + soff + j * 4) = *(uint2*)hb;
                *(uint2*)(nAl + soff + j * 4) = *(uint2*)lb;
            }
        }
        CP_WAIT0();
        __syncthreads();
    }

    const int gid = lane >> 2, tig = lane & 3;
    #pragma unroll
    for (int mi = 0; mi < 4; mi++) {
        int row = m0 + warp_m * 64 + mi * 16 + gid;
        #pragma unroll
        for (int nj = 0; nj < 4; nj++) {
            int col = n0 + warp_n * 32 + nj * 8 + tig * 2;
            *(float2*)&C[(size_t)row * ldc + col] =
                make_float2(acc[mi][nj][0], acc[mi][nj][1]);
            *(float2*)&C[(size_t)(row + 8) * ldc + col] =
                make_float2(acc[mi][nj][2], acc[mi][nj][3]);
        }
    }
}

// ---- pointwise: gate + ve, RoPE, RMSNorm*1.2; Q fp16-split, K/V fp16 ------
__global__ void __launch_bounds__(128) pointwise_kernel(
    const float* __restrict__ x,
    const float* __restrict__ ve,
    const float* __restrict__ cosb,
    const float* __restrict__ sinb,
    const float* __restrict__ Wg)
{
    const int bt   = blockIdx.x;
    const int b    = bt >> 11;
    const int t    = bt & (TT - 1);
    const int tid  = threadIdx.x;
    const int w    = tid >> 5;
    const int lane = tid & 31;

    float p = (lane < 12) ? x[bt * CC + lane] * Wg[lane * NKV + w] : 0.f;
    #pragma unroll
    for (int o = 16; o; o >>= 1) p += __shfl_xor_sync(0xffffffffu, p, o);
    const float gate = 3.f / (1.f + __expf(-p));

    const float c = cosb[t * 32 + lane];
    const float s = sinb[t * 32 + lane];
    const float* qkv = &g_qkv[bt * QKVN];

    for (int h = w; h < NH; h += 4) {
        float x1 = qkv[h * HD + lane];
        float x2 = qkv[h * HD + 32 + lane];
        float y1 =  x1 * c + x2 * s;
        float y2 = -x1 * s + x2 * c;
        float ss = y1 * y1 + y2 * y2;
        #pragma unroll
        for (int o = 16; o; o >>= 1) ss += __shfl_xor_sync(0xffffffffu, ss, o);
        float r = rsqrtf(ss * (1.f / 64.f) + 1e-6f) * 1.2f;
        size_t base = ((size_t)(b * NH + h) * TT + t) * HD;
        __half hi, lo;
        split2h(y1 * r, hi, lo); g_Qh[base + lane]      = hi; g_Ql[base + lane]      = lo;
        split2h(y2 * r, hi, lo); g_Qh[base + lane + 32] = hi; g_Ql[base + lane + 32] = lo;
    }
    {
        float x1 = qkv[1024 + w * HD + lane];
        float x2 = qkv[1024 + w * HD + 32 + lane];
        float y1 =  x1 * c + x2 * s;
        float y2 = -x1 * s + x2 * c;
        float ss = y1 * y1 + y2 * y2;
        #pragma unroll
        for (int o = 16; o; o >>= 1) ss += __shfl_xor_sync(0xffffffffu, ss, o);
        float r = rsqrtf(ss * (1.f / 64.f) + 1e-6f) * 1.2f;
        size_t base = ((size_t)(b * NKV + w) * TT + t) * HD;
        g_Kf[base + lane]      = __float2half(y1 * r);
        g_Kf[base + lane + 32] = __float2half(y2 * r);
    }
    {
        float v1 = qkv[1280 + w * HD + lane]      + gate * ve[bt * (NKV * HD) + w * HD + lane];
        float v2 = qkv[1280 + w * HD + 32 + lane] + gate * ve[bt * (NKV * HD) + w * HD + 32 + lane];
        size_t base = ((size_t)(b * NKV + w) * TT + t) * HD;
        g_Vf[base + lane]      = __float2half(v1);
        g_Vf[base + lane + 32] = __float2half(v2);
    }
}

// ==== fp16 tensor-core flash attention: 128 q-rows/CTA, 8 warps, dbuf K/V ===
#define AP 72
#define AQS (128 * AP)                   // Q array elems
#define AKS (64 * AP)                    // K/V tile array elems
#define ATT_SMEM ((2 * AQS + 4 * AKS) * 2)   // Qh Ql + 2 x (K V)
#define ESC 0.1803368801111204f          // 0.125 * log2(e)

__global__ void __launch_bounds__(256, 2) attn_tc_kernel(const void* __restrict__ winptr)
{
    extern __shared__ __half smh[];
    __half* sQh = smh;
    __half* sQl = smh + AQS;

    const int q0 = (gridDim.x - 1 - blockIdx.x) * 128;
    const int h  = blockIdx.y;
    const int b  = blockIdx.z;
    const int kh = h >> 2;

    const int tid = threadIdx.x, w = tid >> 5, lane = tid & 31;

    int  wi = *(const int*)winptr;
    float wf = *(const float*)winptr;
    const int W = (wi > 0 && wi < (1 << 20)) ? wi : (int)wf;

    const size_t kvbase = (size_t)(b * NKV + kh) * TT * HD;

    const int kr = tid >> 2, kq = tid & 3;
    const uint32_t ksoff = (uint32_t)(kr * AP + kq * 16) * 2;

    int kbeg = q0 - W; if (kbeg < 0) kbeg = 0;
    const int kstart = (kbeg / 64) * 64;
    const int klast  = q0 + 64;

    auto issue_tile = [&](int k0, int bf) {
        const size_t g = kvbase + (size_t)(k0 + kr) * HD + kq * 16;
        uint32_t base = smem_u32(smh + 2 * AQS + bf * 2 * AKS) + ksoff;
        cpa16(base,                g_Kf + g);
        cpa16(base + 16,           g_Kf + g + 8);
        cpa16(base + AKS * 2,      g_Vf + g);
        cpa16(base + AKS * 2 + 16, g_Vf + g + 8);
    };

    {
        const int lr = tid >> 1, lhf = tid & 1;
        size_t gq = ((size_t)(b * NH + h) * TT + q0 + lr) * HD + lhf * 32;
        #pragma unroll
        for (int j = 0; j < 4; j++) {
            *(uint4*)&sQh[lr * AP + lhf * 32 + j * 8] = *(const uint4*)&g_Qh[gq + j * 8];
            *(uint4*)&sQl[lr * AP + lhf * 32 + j * 8] = *(const uint4*)&g_Ql[gq + j * 8];
        }
    }
    issue_tile(kstart, 0);
    CP_COMMIT();
    __syncthreads();

    uint32_t qh[4][4], ql[4][4];
    {
        const int qrow = w * 16 + (lane & 15);
        #pragma unroll
        for (int ks = 0; ks < 4; ks++) {
            int col = ks * 16 + ((lane & 16) ? 8 : 0);
            ldm_x4(smem_u32(&sQh[qrow * AP + col]), qh[ks]);
            ldm_x4(smem_u32(&sQl[qrow * AP + col]), ql[ks]);
        }
    }

    float o[8][4];
    #pragma unroll
    for (int d = 0; d < 8; d++)
        #pragma unroll
        for (int e = 0; e < 4; e++) o[d][e] = 0.f;
    float m_lo = -INFINITY, m_hi = -INFINITY, l_lo = 0.f, l_hi = 0.f;

    const int wmin = q0 + w * 16;
    const int wmax = wmin + 15;
    const int row_lo = wmin + (lane >> 2);
    const int row_hi = row_lo + 8;
    const int colb   = (lane & 3) * 2;

    int buf = 0;
    for (int k0 = kstart; k0 <= klast; k0 += 64) {
        CP_WAIT0();
        __syncthreads();
        if (k0 + 64 <= klast) {
            issue_tile(k0 + 64, buf ^ 1);
            CP_COMMIT();
        }

        const bool active = (k0 <= wmax) && (k0 + 63 >= wmin - W);
        if (active) {
            __half* sK = smh + 2 * AQS + buf * 2 * AKS;
            __half* sV = sK + AKS;

            float s[8][4];
            #pragma unroll
            for (int nj = 0; nj < 8; nj++)
                #pragma unroll
                for (int e = 0; e < 4; e++) s[nj][e] = 0.f;

            #pragma unroll
            for (int ks = 0; ks < 4; ks++) {
                #pragma unroll
                for (int nt = 0; nt < 4; nt++) {
                    int krow = nt * 16 + ((lane & 16) >> 1) + (lane & 7);
                    int col  = ks * 16 + ((lane & 8) ? 8 : 0);
                    uint32_t rk[4];
                    ldm_x4(smem_u32(&sK[krow * AP + col]), rk);
                    #pragma unroll
                    for (int e = 0; e < 2; e++) {
                        uint32_t bf[2] = { rk[e*2], rk[e*2+1] };
                        mma_f16(s[nt*2+e], qh[ks], bf);
                        mma_f16(s[nt*2+e], ql[ks], bf);
                    }
                }
            }

            const bool full = (k0 + 63 <= wmin) && (wmax - k0 <= W);
            if (full) {
                #pragma unroll
                for (int nj = 0; nj < 8; nj++)
                    #pragma unroll
                    for (int e = 0; e < 4; e++) s[nj][e] *= ESC;
            } else {
                #pragma unroll
                for (int nj = 0; nj < 8; nj++) {
                    #pragma unroll
                    for (int e = 0; e < 4; e++) {
                        int col = k0 + nj * 8 + colb + (e & 1);
                        int row = (e < 2) ? row_lo : row_hi;
                        bool ok = (col <= row) && (row - col <= W);
                        s[nj][e] = ok ? s[nj][e] * ESC : -3e9f;
                    }
                }
            }

            float mx_lo = -INFINITY, mx_hi = -INFINITY;
            #pragma unroll
            for (int nj = 0; nj < 8; nj++) {
                mx_lo = fmaxf(mx_lo, fmaxf(s[nj][0], s[nj][1]));
                mx_hi = fmaxf(mx_hi, fmaxf(s[nj][2], s[nj][3]));
            }
            mx_lo = fmaxf(mx_lo, __shfl_xor_sync(0xffffffffu, mx_lo, 1));
            mx_lo = fmaxf(mx_lo, __shfl_xor_sync(0xffffffffu, mx_lo, 2));
            mx_hi = fmaxf(mx_hi, __shfl_xor_sync(0xffffffffu, mx_hi, 1));
            mx_hi = fmaxf(mx_hi, __shfl_xor_sync(0xffffffffu, mx_hi, 2));

            float mnew_lo = fmaxf(fmaxf(m_lo, mx_lo), -1e9f);
            float mnew_hi = fmaxf(fmaxf(m_hi, mx_hi), -1e9f);
            float sc_lo = ex2(m_lo - mnew_lo);
            float sc_hi = ex2(m_hi - mnew_hi);
            m_lo = mnew_lo; m_hi = mnew_hi;

            float sum_lo = 0.f, sum_hi = 0.f;
            #pragma unroll
            for (int nj = 0; nj < 8; nj++) {
                s[nj][0] = ex2(s[nj][0] - mnew_lo);
                s[nj][1] = ex2(s[nj][1] - mnew_lo);
                s[nj][2] = ex2(s[nj][2] - mnew_hi);
                s[nj][3] = ex2(s[nj][3] - mnew_hi);
                sum_lo += s[nj][0] + s[nj][1];
                sum_hi += s[nj][2] + s[nj][3];
            }
            sum_lo += __shfl_xor_sync(0xffffffffu, sum_lo, 1);
            sum_lo += __shfl_xor_sync(0xffffffffu, sum_lo, 2);
            sum_hi += __shfl_xor_sync(0xffffffffu, sum_hi, 1);
            sum_hi += __shfl_xor_sync(0xffffffffu, sum_hi, 2);
            l_lo = l_lo * sc_lo + sum_lo;
            l_hi = l_hi * sc_hi + sum_hi;

            #pragma unroll
            for (int d = 0; d < 8; d++) {
                o[d][0] *= sc_lo; o[d][1] *= sc_lo;
                o[d][2] *= sc_hi; o[d][3] *= sc_hi;
            }

            #pragma unroll
            for (int ks = 0; ks < 4; ks++) {
                uint32_t ph[4], pl[4];
                #pragma unroll
                for (int e = 0; e < 2; e++) {
                    int nj = ks * 2 + e;
                    float p0 = s[nj][0], p1 = s[nj][1], p2 = s[nj][2], p3 = s[nj][3];
                    uint32_t h01 = packh(p0, p1);
                    uint32_t h23 = packh(p2, p3);
                    __half2 v01 = *(__half2*)&h01;
                    __half2 v23 = *(__half2*)&h23;
                    pl[e*2]   = packh(p0 - __half2float(v01.x),
                                      p1 - __half2float(v01.y));
                    pl[e*2+1] = packh(p2 - __half2float(v23.x),
                                      p3 - __half2float(v23.y));
                    ph[e*2]   = h01; ph[e*2+1] = h23;
                }
                #pragma unroll
                for (int dt = 0; dt < 4; dt++) {
                    int vrow = ks * 16 + (lane & 15);
                    int vcol = dt * 16 + ((lane & 16) ? 8 : 0);
                    uint32_t rv[4];
                    ldm_x4t(smem_u32(&sV[vrow * AP + vcol]), rv);
                    #pragma unroll
                    for (int e = 0; e < 2; e++) {
                        uint32_t bf[2] = { rv[e*2], rv[e*2+1] };
                        mma_f16(o[dt*2+e], ph, bf);
                        mma_f16(o[dt*2+e], pl, bf);
                    }
                }
            }
        }
        buf ^= 1;
    }

    float li_lo = 1.f / l_lo, li_hi = 1.f / l_hi;
    #pragma unroll
    for (int d = 0; d < 8; d++) {
        int col = h * HD + d * 8 + colb;
        *(float2*)&g_Y[(size_t)(b * TT + row_lo) * CC + col] =
            make_float2(o[d][0] * li_lo, o[d][1] * li_lo);
        *(float2*)&g_Y[(size_t)(b * TT + row_hi) * CC + col] =
            make_float2(o[d][2] * li_hi, o[d][3] * li_hi);
    }
}

// ---------------------------------------------------------------------------
extern "C" void kernel_launch(void* const* d_in, const int* in_sizes, int n_in,
                              void* d_out, int out_size)
{
    const float* x    = (const float*)d_in[0];
    const float* ve   = (const float*)d_in[1];
    const float* cosb = (const float*)d_in[2];
    const float* sinb = (const float*)d_in[3];
    const float* Wq   = (const float*)d_in[4];
    const float* Wk   = (const float*)d_in[5];
    const float* Wv   = (const float*)d_in[6];
    const float* Wp   = (const float*)d_in[7];
    const float* Wg   = (const float*)d_in[8];
    const void*  win  = d_in[9];
    float* out = (float*)d_out;

    cudaFuncSetAttribute(attn_tc_kernel, cudaFuncAttributeMaxDynamicSharedMemorySize,
                         ATT_SMEM);
    cudaFuncSetAttribute(tc_gemm, cudaFuncAttributeMaxDynamicSharedMemorySize,
                         GEMM_SMEM);

    __half *wfp, *pfp;
    cudaGetSymbolAddress((void**)&wfp, g_wf);
    cudaGetSymbolAddress((void**)&pfp, g_pf);
    float *qkvp, *Yp;
    cudaGetSymbolAddress((void**)&qkvp, g_qkv);
    cudaGetSymbolAddress((void**)&Yp, g_Y);

    // all weight transposes in ONE launch
    wtrans_all_kernel<<<dim3(32, 32, 4), 256>>>(Wq, Wk, Wv, Wp, wfp, pfp);

    // qkv = x @ [Wq|Wk|Wv]
    tc_gemm<<<dim3(12, 32), 256, GEMM_SMEM>>>(x, wfp, qkvp, 1024, QKVN);

    pointwise_kernel<<<MTOT, 128>>>(x, ve, cosb, sinb, Wg);

    attn_tc_kernel<<<dim3(TT / 128, NH, BB), 256, ATT_SMEM>>>(win);

    // out = Y @ Wproj
    tc_gemm<<<dim3(8, 32), 256, GEMM_SMEM>>>(Yp, pfp, out, 1024, 1024);
}